// round 1
// baseline (speedup 1.0000x reference)
#include <cuda_runtime.h>
#include <math.h>

#define NBV   336      // B*NV
#define BSZ   16
#define NVAR  21
#define TT    512
#define TP    520      // padded series length
#define PNUM  64       // patches
#define DM    128
#define SEA   512
#define DIN   256
#define DSS   16
#define LSEQ  64
#define PRED  96
#define EPS_F 1e-5f

// ---------------- scratch (device globals; no allocation) ----------------
__device__ float g_xn[NBV * TP];
__device__ float g_mean[NBV];
__device__ float g_std[NBV];
__device__ float g_h [NBV * PNUM * DM];
__device__ float g_hb[NBV * PNUM * DM];
__device__ float g_xc  [NBV * LSEQ * DIN];
__device__ float g_z   [NBV * LSEQ * DIN];
__device__ float g_xcc [NBV * LSEQ * DIN];
__device__ float g_delta[NBV * LSEQ * DIN];
__device__ float g_BC  [NBV * LSEQ * 32];
__device__ float g_y   [NBV * LSEQ * DIN];
__device__ float g_mo  [NBV * PNUM * DM];   // mamba out, (bv, p*128+d)
__device__ float g_t2  [NBV * 192];

__device__ __forceinline__ float gelu_exact(float x) {
    return 0.5f * x * (1.0f + erff(x * 0.70710678118654752f));
}
__device__ __forceinline__ float silu_f(float x) {
    return x / (1.0f + __expf(-x));
}

// ---------------- K1: RevIN stats + normalize + pad ----------------
__global__ void k_revin(const float* __restrict__ x,
                        const float* __restrict__ rw, const float* __restrict__ rb) {
    int bv = blockIdx.x;
    int b = bv / NVAR, v = bv % NVAR;
    int t = threadIdx.x;  // 512 threads
    float val = x[(size_t)(b * TT + t) * NVAR + v];

    __shared__ float s1[16], s2[16];
    float a = val, q = val * val;
    #pragma unroll
    for (int o = 16; o; o >>= 1) {
        a += __shfl_down_sync(0xffffffffu, a, o);
        q += __shfl_down_sync(0xffffffffu, q, o);
    }
    if ((t & 31) == 0) { s1[t >> 5] = a; s2[t >> 5] = q; }
    __syncthreads();
    __shared__ float mb[2];
    if (t < 32) {
        float a2 = (t < 16) ? s1[t] : 0.f;
        float q2 = (t < 16) ? s2[t] : 0.f;
        #pragma unroll
        for (int o = 8; o; o >>= 1) {
            a2 += __shfl_down_sync(0xffffffffu, a2, o);
            q2 += __shfl_down_sync(0xffffffffu, q2, o);
        }
        if (t == 0) {
            float mean = a2 * (1.0f / TT);
            float var  = q2 * (1.0f / TT) - mean * mean;
            float sd   = sqrtf(var + EPS_F);
            mb[0] = mean; mb[1] = sd;
            g_mean[bv] = mean; g_std[bv] = sd;
        }
    }
    __syncthreads();
    float xnv = (val - mb[0]) / mb[1] * rw[v] + rb[v];
    g_xn[bv * TP + t] = xnv;
    if (t == TT - 1) {
        #pragma unroll
        for (int i = 0; i < 8; i++) g_xn[bv * TP + TT + i] = xnv;
    }
}

// ---------------- K2: patches @ mlp1_w.T + b ----------------
__global__ void k_mlp1(const float* __restrict__ w, const float* __restrict__ bias) {
    int bv = blockIdx.x;
    int d = threadIdx.x;  // 128
    __shared__ float xs[TP];
    for (int i = d; i < TP; i += 128) xs[i] = g_xn[bv * TP + i];
    float wr[16];
    #pragma unroll
    for (int s = 0; s < 16; s++) wr[s] = w[d * 16 + s];
    float bb = bias[d];
    __syncthreads();
    float* hp = g_h + (size_t)bv * PNUM * DM;
    #pragma unroll 4
    for (int p = 0; p < PNUM; p++) {
        float acc = bb;
        const float* xp = xs + p * 8;
        #pragma unroll
        for (int s = 0; s < 16; s++) acc = fmaf(xp[s], wr[s], acc);
        hp[p * DM + d] = acc;
    }
}

// ---------------- K3: external attention + LN + GELU + residual ----------------
// grid 336, block 256. static smem = 48KB exactly.
__global__ void k_attn(const float* __restrict__ mk, const float* __restrict__ mv,
                       const float* __restrict__ lnw, const float* __restrict__ lnb) {
    __shared__ float hs[PNUM * DM];   // 8192 floats
    __shared__ float ps[8 * SEA];     // 4096 floats
    int bv = blockIdx.x;
    int tid = threadIdx.x;            // 256
    const float* hg = g_h + (size_t)bv * PNUM * DM;
    float* hbg = g_hb + (size_t)bv * PNUM * DM;
    for (int i = tid; i < PNUM * DM; i += 256) hs[i] = hg[i];
    __syncthreads();

    for (int pg = 0; pg < 8; pg++) {
        // ---- scores: 8 rows x 512 cols ----
        #pragma unroll
        for (int jj = 0; jj < 2; jj++) {
            int j = tid + jj * 256;
            const float4* w4 = (const float4*)(mk + (size_t)j * DM);
            float acc[8];
            #pragma unroll
            for (int r = 0; r < 8; r++) acc[r] = 0.f;
            for (int k = 0; k < 32; k++) {
                float4 bq = w4[k];
                #pragma unroll
                for (int r = 0; r < 8; r++) {
                    float4 aq = *(const float4*)(hs + (pg * 8 + r) * DM + k * 4);
                    acc[r] = fmaf(aq.x, bq.x, acc[r]);
                    acc[r] = fmaf(aq.y, bq.y, acc[r]);
                    acc[r] = fmaf(aq.z, bq.z, acc[r]);
                    acc[r] = fmaf(aq.w, bq.w, acc[r]);
                }
            }
            #pragma unroll
            for (int r = 0; r < 8; r++) ps[r * SEA + j] = acc[r];
        }
        __syncthreads();
        // ---- softmax (warp w owns row w) ----
        {
            int w = tid >> 5, lane = tid & 31;
            float mx = -1e30f;
            for (int j = lane; j < SEA; j += 32) mx = fmaxf(mx, ps[w * SEA + j]);
            #pragma unroll
            for (int o = 16; o; o >>= 1) mx = fmaxf(mx, __shfl_xor_sync(0xffffffffu, mx, o));
            float sum = 0.f;
            for (int j = lane; j < SEA; j += 32) {
                float e = __expf(ps[w * SEA + j] - mx);
                ps[w * SEA + j] = e;
                sum += e;
            }
            #pragma unroll
            for (int o = 16; o; o >>= 1) sum += __shfl_xor_sync(0xffffffffu, sum, o);
            float inv = 1.0f / sum;
            for (int j = lane; j < SEA; j += 32) ps[w * SEA + j] *= inv;
        }
        __syncthreads();
        // ---- attn @ mv.T, then LN + GELU + residual (warp r owns row r) ----
        {
            int r = tid >> 5, lane = tid & 31;
            const float4* p4 = (const float4*)(ps + r * SEA);
            float od[4];
            #pragma unroll
            for (int i = 0; i < 4; i++) {
                int d = lane + i * 32;
                const float4* mv4 = (const float4*)(mv + (size_t)d * SEA);
                float acc = 0.f;
                for (int k = 0; k < 128; k++) {
                    float4 aq = p4[k]; float4 bq = mv4[k];
                    acc = fmaf(aq.x, bq.x, acc);
                    acc = fmaf(aq.y, bq.y, acc);
                    acc = fmaf(aq.z, bq.z, acc);
                    acc = fmaf(aq.w, bq.w, acc);
                }
                od[i] = acc;
            }
            float s = od[0] + od[1] + od[2] + od[3];
            float q = od[0]*od[0] + od[1]*od[1] + od[2]*od[2] + od[3]*od[3];
            #pragma unroll
            for (int o = 16; o; o >>= 1) {
                s += __shfl_xor_sync(0xffffffffu, s, o);
                q += __shfl_xor_sync(0xffffffffu, q, o);
            }
            float mu = s * (1.0f / DM);
            float var = q * (1.0f / DM) - mu * mu;
            float istd = rsqrtf(var + EPS_F);
            int row = pg * 8 + r;
            #pragma unroll
            for (int i = 0; i < 4; i++) {
                int d = lane + i * 32;
                float ln = (od[i] - mu) * istd * lnw[d] + lnb[d];
                hbg[row * DM + d] = gelu_exact(ln) + hs[row * DM + d];
            }
        }
        __syncthreads();
    }
}

// ---------------- K4: in_proj (64x128 @ 128x512) -> xc, z ----------------
__global__ void k_inproj(const float* __restrict__ W) {
    int bv = blockIdx.x, tid = threadIdx.x;  // 256
    __shared__ float hs[PNUM * DM];  // 32KB
    const float* hbg = g_hb + (size_t)bv * PNUM * DM;
    for (int i = tid; i < PNUM * DM; i += 256) hs[i] = hbg[i];
    __syncthreads();
    #pragma unroll
    for (int jj = 0; jj < 2; jj++) {
        int j = tid + jj * 256;
        const float4* w4 = (const float4*)(W + (size_t)j * DM);
        float* dst = (jj == 0 ? g_xc : g_z) + (size_t)bv * LSEQ * DIN;
        for (int half = 0; half < 2; half++) {
            float acc[32];
            #pragma unroll
            for (int l = 0; l < 32; l++) acc[l] = 0.f;
            for (int k = 0; k < 32; k++) {
                float4 bq = w4[k];
                #pragma unroll
                for (int l = 0; l < 32; l++) {
                    float4 aq = *(const float4*)(hs + (half * 32 + l) * DM + k * 4);
                    acc[l] = fmaf(aq.x, bq.x, acc[l]);
                    acc[l] = fmaf(aq.y, bq.y, acc[l]);
                    acc[l] = fmaf(aq.z, bq.z, acc[l]);
                    acc[l] = fmaf(aq.w, bq.w, acc[l]);
                }
            }
            #pragma unroll
            for (int l = 0; l < 32; l++) dst[(half * 32 + l) * DIN + tid] = acc[l];
        }
    }
}

// ---------------- K5a: depthwise causal conv (DC=4) + bias + SiLU ----------------
__global__ void k_conv(const float* __restrict__ cw, const float* __restrict__ cb) {
    int bv = blockIdx.x, c = threadIdx.x;  // 256
    const float* xp = g_xc + (size_t)bv * LSEQ * DIN;
    float* op = g_xcc + (size_t)bv * LSEQ * DIN;
    float w0 = cw[c * 4 + 0], w1 = cw[c * 4 + 1], w2 = cw[c * 4 + 2], w3 = cw[c * 4 + 3];
    float bb = cb[c];
    float xm3 = 0.f, xm2 = 0.f, xm1 = 0.f;
    for (int l = 0; l < LSEQ; l++) {
        float xv = xp[l * DIN + c];
        float t = fmaf(xm3, w0, fmaf(xm2, w1, fmaf(xm1, w2, fmaf(xv, w3, bb))));
        op[l * DIN + c] = silu_f(t);
        xm3 = xm2; xm2 = xm1; xm1 = xv;
    }
}

// ---------------- K5b: x_proj (-> dt,B,C) + dt_proj + softplus ----------------
__global__ void k_xproj(const float* __restrict__ xpw,
                        const float* __restrict__ dtw, const float* __restrict__ dtb) {
    int bv = blockIdx.x, tid = threadIdx.x;  // 256
    __shared__ float xs[8 * DIN];     // 8KB
    __shared__ float dbl[LSEQ * 40];  // 10KB
    const float* xcc = g_xcc + (size_t)bv * LSEQ * DIN;

    for (int lt = 0; lt < 8; lt++) {
        for (int i = tid; i < 8 * DIN; i += 256) xs[i] = xcc[lt * 8 * DIN + i];
        __syncthreads();
        int w = tid >> 5, lane = tid & 31;
        const float* xr = xs + w * DIN;
        for (int o = lane; o < 40; o += 32) {
            const float4* wp = (const float4*)(xpw + o * DIN);
            const float4* x4 = (const float4*)xr;
            float acc = 0.f;
            for (int k = 0; k < 64; k++) {
                float4 aq = x4[k]; float4 bq = wp[k];
                acc = fmaf(aq.x, bq.x, acc);
                acc = fmaf(aq.y, bq.y, acc);
                acc = fmaf(aq.z, bq.z, acc);
                acc = fmaf(aq.w, bq.w, acc);
            }
            dbl[(lt * 8 + w) * 40 + o] = acc;
        }
        __syncthreads();
    }
    // delta = softplus(dt @ dt_proj_w.T + b)
    int c = tid;
    float dw[8];
    #pragma unroll
    for (int r = 0; r < 8; r++) dw[r] = dtw[c * 8 + r];
    float db = dtb[c];
    float* dp = g_delta + (size_t)bv * LSEQ * DIN;
    for (int l = 0; l < LSEQ; l++) {
        float acc = db;
        #pragma unroll
        for (int r = 0; r < 8; r++) acc = fmaf(dbl[l * 40 + r], dw[r], acc);
        dp[l * DIN + c] = (acc > 20.f) ? acc : log1pf(expf(acc));
    }
    // copy B,C
    float* bc = g_BC + (size_t)bv * LSEQ * 32;
    for (int i = tid; i < LSEQ * 32; i += 256) {
        int l = i >> 5, s = i & 31;
        bc[i] = dbl[l * 40 + 8 + s];
    }
}

// ---------------- K6: selective scan + D skip + SiLU(z) gate ----------------
__global__ void k_scan(const float* __restrict__ A_log, const float* __restrict__ D_ssm) {
    int bv = blockIdx.x, c = threadIdx.x;  // 256
    __shared__ float bc[LSEQ * 32];
    for (int i = c; i < LSEQ * 32; i += 256) bc[i] = g_BC[(size_t)bv * LSEQ * 32 + i];
    float As[DSS];
    #pragma unroll
    for (int s = 0; s < DSS; s++) As[s] = -expf(A_log[c * DSS + s]);
    float Dv = D_ssm[c];
    float st[DSS];
    #pragma unroll
    for (int s = 0; s < DSS; s++) st[s] = 0.f;
    __syncthreads();
    size_t base = (size_t)bv * LSEQ * DIN;
    for (int l = 0; l < LSEQ; l++) {
        float d  = g_delta[base + l * DIN + c];
        float u  = g_xcc  [base + l * DIN + c];
        float zv = g_z    [base + l * DIN + c];
        float du = d * u;
        float y = 0.f;
        #pragma unroll
        for (int s = 0; s < DSS; s++) {
            float dA = __expf(d * As[s]);
            st[s] = fmaf(st[s], dA, du * bc[l * 32 + s]);
            y = fmaf(st[s], bc[l * 32 + 16 + s], y);
        }
        y = fmaf(Dv, u, y);
        y *= silu_f(zv);
        g_y[base + l * DIN + c] = y;
    }
}

// ---------------- K7: out_proj (64x256 @ 256x128) ----------------
__global__ void k_outproj(const float* __restrict__ W) {
    int bv = blockIdx.x, d = threadIdx.x;  // 128
    __shared__ float ys[32 * DIN];  // 32KB
    const float* yg = g_y + (size_t)bv * LSEQ * DIN;
    float* mo = g_mo + (size_t)bv * PNUM * DM;
    const float4* w4 = (const float4*)(W + (size_t)d * DIN);
    for (int half = 0; half < 2; half++) {
        for (int i = d; i < 32 * DIN; i += 128) ys[i] = yg[half * 32 * DIN + i];
        __syncthreads();
        float acc[32];
        #pragma unroll
        for (int l = 0; l < 32; l++) acc[l] = 0.f;
        for (int k = 0; k < 64; k++) {
            float4 bq = w4[k];
            #pragma unroll
            for (int l = 0; l < 32; l++) {
                float4 aq = *(const float4*)(ys + l * DIN + k * 4);
                acc[l] = fmaf(aq.x, bq.x, acc[l]);
                acc[l] = fmaf(aq.y, bq.y, acc[l]);
                acc[l] = fmaf(aq.z, bq.z, acc[l]);
                acc[l] = fmaf(aq.w, bq.w, acc[l]);
            }
        }
        #pragma unroll
        for (int l = 0; l < 32; l++) mo[(half * 32 + l) * DM + d] = acc[l];
        __syncthreads();
    }
}

// ---------------- K8a: mlp2 (336x8192 @ 8192x192) + GELU ----------------
// grid (28, 6), block 128: 12 rows x 32 cols per block; thread = (r3, o), 3 rows each
__global__ void k_mlp2(const float* __restrict__ W, const float* __restrict__ bias) {
    int mt = blockIdx.x, nt = blockIdx.y;
    int tid = threadIdx.x;
    int o = tid & 31, r3 = tid >> 5;
    int col = nt * 32 + o;
    __shared__ float in_s[12 * 512];  // 24KB
    float acc0 = 0.f, acc1 = 0.f, acc2 = 0.f;
    for (int kc = 0; kc < 16; kc++) {
        for (int i = tid; i < 12 * 512; i += 128) {
            int rr = i >> 9, k = i & 511;
            in_s[i] = g_mo[(size_t)(mt * 12 + rr) * 8192 + kc * 512 + k];
        }
        __syncthreads();
        const float4* w4 = (const float4*)(W + (size_t)col * 8192 + kc * 512);
        const float4* a0 = (const float4*)(in_s + (r3 * 3 + 0) * 512);
        const float4* a1 = (const float4*)(in_s + (r3 * 3 + 1) * 512);
        const float4* a2 = (const float4*)(in_s + (r3 * 3 + 2) * 512);
        #pragma unroll 4
        for (int k = 0; k < 128; k++) {
            float4 bq = w4[k];
            float4 x0 = a0[k];
            acc0 = fmaf(x0.x, bq.x, acc0); acc0 = fmaf(x0.y, bq.y, acc0);
            acc0 = fmaf(x0.z, bq.z, acc0); acc0 = fmaf(x0.w, bq.w, acc0);
            float4 x1 = a1[k];
            acc1 = fmaf(x1.x, bq.x, acc1); acc1 = fmaf(x1.y, bq.y, acc1);
            acc1 = fmaf(x1.z, bq.z, acc1); acc1 = fmaf(x1.w, bq.w, acc1);
            float4 x2 = a2[k];
            acc2 = fmaf(x2.x, bq.x, acc2); acc2 = fmaf(x2.y, bq.y, acc2);
            acc2 = fmaf(x2.z, bq.z, acc2); acc2 = fmaf(x2.w, bq.w, acc2);
        }
        __syncthreads();
    }
    float bb = bias[col];
    int row0 = mt * 12 + r3 * 3;
    g_t2[(size_t)(row0 + 0) * 192 + col] = gelu_exact(acc0 + bb);
    g_t2[(size_t)(row0 + 1) * 192 + col] = gelu_exact(acc1 + bb);
    g_t2[(size_t)(row0 + 2) * 192 + col] = gelu_exact(acc2 + bb);
}

// ---------------- K8b: mlp3 + transpose + RevIN denorm ----------------
__global__ void k_mlp3(const float* __restrict__ W3, const float* __restrict__ b3,
                       const float* __restrict__ rw, const float* __restrict__ rb,
                       float* __restrict__ out) {
    int bv = blockIdx.x;
    int b = bv / NVAR, v = bv % NVAR;
    int tid = threadIdx.x;  // 192
    __shared__ float ts[192];
    ts[tid] = g_t2[(size_t)bv * 192 + tid];
    __syncthreads();
    if (tid < PRED) {
        float acc = b3[tid];
        const float* w = W3 + tid * 192;
        #pragma unroll 4
        for (int j = 0; j < 192; j++) acc = fmaf(ts[j], w[j], acc);
        float val = (acc - rb[v]) / (rw[v] + 1e-10f) * g_std[bv] + g_mean[bv];
        out[((size_t)b * PRED + tid) * NVAR + v] = val;
    }
}

// ---------------- launch ----------------
extern "C" void kernel_launch(void* const* d_in, const int* in_sizes, int n_in,
                              void* d_out, int out_size) {
    const float* x         = (const float*)d_in[0];
    const float* revin_w   = (const float*)d_in[1];
    const float* revin_b   = (const float*)d_in[2];
    const float* mlp1_w    = (const float*)d_in[3];
    const float* mlp1_b    = (const float*)d_in[4];
    const float* mk_w      = (const float*)d_in[5];
    const float* mv_w      = (const float*)d_in[6];
    const float* ln_w      = (const float*)d_in[7];
    const float* ln_b      = (const float*)d_in[8];
    const float* in_proj_w = (const float*)d_in[9];
    const float* conv_w    = (const float*)d_in[10];
    const float* conv_b    = (const float*)d_in[11];
    const float* x_proj_w  = (const float*)d_in[12];
    const float* dt_proj_w = (const float*)d_in[13];
    const float* dt_proj_b = (const float*)d_in[14];
    const float* A_log     = (const float*)d_in[15];
    const float* D_ssm     = (const float*)d_in[16];
    const float* out_proj_w= (const float*)d_in[17];
    const float* mlp2_w    = (const float*)d_in[18];
    const float* mlp2_b    = (const float*)d_in[19];
    const float* mlp3_w    = (const float*)d_in[20];
    const float* mlp3_b    = (const float*)d_in[21];
    float* out = (float*)d_out;

    k_revin  <<<NBV, 512>>>(x, revin_w, revin_b);
    k_mlp1   <<<NBV, 128>>>(mlp1_w, mlp1_b);
    k_attn   <<<NBV, 256>>>(mk_w, mv_w, ln_w, ln_b);
    k_inproj <<<NBV, 256>>>(in_proj_w);
    k_conv   <<<NBV, 256>>>(conv_w, conv_b);
    k_xproj  <<<NBV, 256>>>(x_proj_w, dt_proj_w, dt_proj_b);
    k_scan   <<<NBV, 256>>>(A_log, D_ssm);
    k_outproj<<<NBV, 128>>>(out_proj_w);
    dim3 g2(28, 6);
    k_mlp2   <<<g2, 128>>>(mlp2_w, mlp2_b);
    k_mlp3   <<<NBV, 192>>>(mlp3_w, mlp3_b, revin_w, revin_b, out);
}

// round 4
// speedup vs baseline: 3.8815x; 3.8815x over previous
#include <cuda_runtime.h>
#include <math.h>

#define NBV   336      // B*NV
#define NVAR  21
#define TT    512
#define TP    520
#define PNUM  64
#define DM    128
#define SEA   512
#define DIN   256
#define DSS   16
#define LSEQ  64
#define PRED  96
#define EPS_F 1e-5f
#define MROWS (NBV * PNUM)   // 21504 global rows

// ---------------- scratch ----------------
__device__ float g_xn[NBV * TP];
__device__ float g_mean[NBV];
__device__ float g_std[NBV];
__device__ float g_h [MROWS * DM];
__device__ float g_hb[MROWS * DM];
__device__ float g_ps[MROWS * SEA];          // 44MB attention scores
__device__ float g_xc  [MROWS * DIN];        // xc rows are (bv,l) pairs: 21504 x 256
__device__ float g_z   [MROWS * DIN];
__device__ float g_xcc [MROWS * DIN];
__device__ float g_delta[MROWS * DIN];
__device__ float g_BC  [NBV * LSEQ * 32];
__device__ float g_y   [MROWS * DIN];
__device__ float g_mo  [MROWS * DM];
__device__ float g_t2p [16 * NBV * 192];
__device__ float g_t2  [NBV * 192];

__device__ __forceinline__ float gelu_exact(float x) {
    return 0.5f * x * (1.0f + erff(x * 0.70710678118654752f));
}
__device__ __forceinline__ float silu_f(float x) {
    return x / (1.0f + __expf(-x));
}

// ---------------- generic 64x64 tile GEMM core (NT: C = A[M,K] * B[N,K]^T) ----
// 128 threads. acc[8][4]; tx = tid&15 (cols), ty = tid>>4 (rows).
__device__ __forceinline__ void gemm64(const float* __restrict__ A, int lda,
                                       const float* __restrict__ Bn,  // pre-offset to n0 row
                                       int ldb, int m0, int K, int Mmax,
                                       float As[16][64], float Bs[16][64],
                                       float acc[8][4], int tx, int ty) {
    int tid = threadIdx.x;
    for (int k0 = 0; k0 < K; k0 += 16) {
        #pragma unroll
        for (int u = 0; u < 2; u++) {
            int f = tid * 2 + u, row = f >> 2, kq = f & 3;
            float4 v = make_float4(0.f, 0.f, 0.f, 0.f);
            int gr = m0 + row;
            if (gr < Mmax) v = *(const float4*)(A + (size_t)gr * lda + k0 + kq * 4);
            As[kq * 4 + 0][row] = v.x; As[kq * 4 + 1][row] = v.y;
            As[kq * 4 + 2][row] = v.z; As[kq * 4 + 3][row] = v.w;
        }
        #pragma unroll
        for (int u = 0; u < 2; u++) {
            int f = tid * 2 + u, row = f >> 2, kq = f & 3;
            float4 v = *(const float4*)(Bn + (size_t)row * ldb + k0 + kq * 4);
            Bs[kq * 4 + 0][row] = v.x; Bs[kq * 4 + 1][row] = v.y;
            Bs[kq * 4 + 2][row] = v.z; Bs[kq * 4 + 3][row] = v.w;
        }
        __syncthreads();
        #pragma unroll
        for (int kk = 0; kk < 16; kk++) {
            float4 a0 = *(const float4*)&As[kk][ty * 8];
            float4 a1 = *(const float4*)&As[kk][ty * 8 + 4];
            float4 b  = *(const float4*)&Bs[kk][tx * 4];
            float av[8] = {a0.x, a0.y, a0.z, a0.w, a1.x, a1.y, a1.z, a1.w};
            float bv[4] = {b.x, b.y, b.z, b.w};
            #pragma unroll
            for (int i = 0; i < 8; i++)
                #pragma unroll
                for (int j = 0; j < 4; j++)
                    acc[i][j] = fmaf(av[i], bv[j], acc[i][j]);
        }
        __syncthreads();
    }
}

// ---------------- K1: RevIN ----------------
__global__ void k_revin(const float* __restrict__ x,
                        const float* __restrict__ rw, const float* __restrict__ rb) {
    int bv = blockIdx.x;
    int b = bv / NVAR, v = bv % NVAR;
    int t = threadIdx.x;
    float val = x[(size_t)(b * TT + t) * NVAR + v];
    __shared__ float s1[16], s2[16];
    float a = val, q = val * val;
    #pragma unroll
    for (int o = 16; o; o >>= 1) {
        a += __shfl_down_sync(0xffffffffu, a, o);
        q += __shfl_down_sync(0xffffffffu, q, o);
    }
    if ((t & 31) == 0) { s1[t >> 5] = a; s2[t >> 5] = q; }
    __syncthreads();
    __shared__ float mb[2];
    if (t < 32) {
        float a2 = (t < 16) ? s1[t] : 0.f;
        float q2 = (t < 16) ? s2[t] : 0.f;
        #pragma unroll
        for (int o = 8; o; o >>= 1) {
            a2 += __shfl_down_sync(0xffffffffu, a2, o);
            q2 += __shfl_down_sync(0xffffffffu, q2, o);
        }
        if (t == 0) {
            float mean = a2 * (1.0f / TT);
            float var  = q2 * (1.0f / TT) - mean * mean;
            float sd   = sqrtf(var + EPS_F);
            mb[0] = mean; mb[1] = sd;
            g_mean[bv] = mean; g_std[bv] = sd;
        }
    }
    __syncthreads();
    float xnv = (val - mb[0]) / mb[1] * rw[v] + rb[v];
    g_xn[bv * TP + t] = xnv;
    if (t == TT - 1) {
        #pragma unroll
        for (int i = 0; i < 8; i++) g_xn[bv * TP + TT + i] = xnv;
    }
}

// ---------------- K2: mlp1 ----------------
__global__ void k_mlp1(const float* __restrict__ w, const float* __restrict__ bias) {
    int bv = blockIdx.x;
    int d = threadIdx.x;
    __shared__ float xs[TP];
    for (int i = d; i < TP; i += 128) xs[i] = g_xn[bv * TP + i];
    float wr[16];
    #pragma unroll
    for (int s = 0; s < 16; s++) wr[s] = w[d * 16 + s];
    float bb = bias[d];
    __syncthreads();
    float* hp = g_h + (size_t)bv * PNUM * DM;
    #pragma unroll 4
    for (int p = 0; p < PNUM; p++) {
        float acc = bb;
        const float* xp = xs + p * 8;
        #pragma unroll
        for (int s = 0; s < 16; s++) acc = fmaf(xp[s], wr[s], acc);
        hp[p * DM + d] = acc;
    }
}

// ---------------- K3a: scores = h @ mk^T (21504x512x128) ----------------
__global__ void __launch_bounds__(128) k_scores(const float* __restrict__ mk) {
    __shared__ float As[16][64], Bs[16][64];
    float acc[8][4];
    #pragma unroll
    for (int i = 0; i < 8; i++)
        #pragma unroll
        for (int j = 0; j < 4; j++) acc[i][j] = 0.f;
    int tid = threadIdx.x, tx = tid & 15, ty = tid >> 4;
    int m0 = blockIdx.x * 64, n0 = blockIdx.y * 64;
    gemm64(g_h, DM, mk + (size_t)n0 * DM, DM, m0, DM, 1 << 30, As, Bs, acc, tx, ty);
    #pragma unroll
    for (int i = 0; i < 8; i++) {
        int gr = m0 + ty * 8 + i;
        *(float4*)&g_ps[(size_t)gr * SEA + n0 + tx * 4] =
            make_float4(acc[i][0], acc[i][1], acc[i][2], acc[i][3]);
    }
}

// ---------------- K3b: row softmax over 512 ----------------
__global__ void k_softmax() {
    int tid = threadIdx.x, lane = tid & 31, w = tid >> 5;
    int row = blockIdx.x * 4 + w;
    float4* base = (float4*)(g_ps + (size_t)row * SEA);
    float4 v[4];
    float mx = -1e30f;
    #pragma unroll
    for (int q = 0; q < 4; q++) {
        v[q] = base[q * 32 + lane];
        mx = fmaxf(mx, fmaxf(fmaxf(v[q].x, v[q].y), fmaxf(v[q].z, v[q].w)));
    }
    #pragma unroll
    for (int o = 16; o; o >>= 1) mx = fmaxf(mx, __shfl_xor_sync(0xffffffffu, mx, o));
    float sum = 0.f;
    #pragma unroll
    for (int q = 0; q < 4; q++) {
        v[q].x = __expf(v[q].x - mx); v[q].y = __expf(v[q].y - mx);
        v[q].z = __expf(v[q].z - mx); v[q].w = __expf(v[q].w - mx);
        sum += v[q].x + v[q].y + v[q].z + v[q].w;
    }
    #pragma unroll
    for (int o = 16; o; o >>= 1) sum += __shfl_xor_sync(0xffffffffu, sum, o);
    float inv = 1.0f / sum;
    #pragma unroll
    for (int q = 0; q < 4; q++) {
        v[q].x *= inv; v[q].y *= inv; v[q].z *= inv; v[q].w *= inv;
        base[q * 32 + lane] = v[q];
    }
}

// ---------------- K3c: AV = P @ mv^T (21504x128x512), fused LN+GELU+residual ----
// 256 threads, tile 64x128
__global__ void __launch_bounds__(256) k_av(const float* __restrict__ mv,
                     const float* __restrict__ lnw, const float* __restrict__ lnb) {
    __shared__ float As[16][64];
    __shared__ float Bs[16][128];
    __shared__ float Cs[64][128];
    int tid = threadIdx.x, tx = tid & 31, ty = tid >> 5;
    int m0 = blockIdx.x * 64;
    float acc[8][4];
    #pragma unroll
    for (int i = 0; i < 8; i++)
        #pragma unroll
        for (int j = 0; j < 4; j++) acc[i][j] = 0.f;
    for (int k0 = 0; k0 < SEA; k0 += 16) {
        {
            int f = tid, row = f >> 2, kq = f & 3;
            float4 v = *(const float4*)(g_ps + (size_t)(m0 + row) * SEA + k0 + kq * 4);
            As[kq * 4 + 0][row] = v.x; As[kq * 4 + 1][row] = v.y;
            As[kq * 4 + 2][row] = v.z; As[kq * 4 + 3][row] = v.w;
        }
        #pragma unroll
        for (int u = 0; u < 2; u++) {
            int f = tid * 2 + u, row = f >> 2, kq = f & 3;
            float4 v = *(const float4*)(mv + (size_t)row * SEA + k0 + kq * 4);
            Bs[kq * 4 + 0][row] = v.x; Bs[kq * 4 + 1][row] = v.y;
            Bs[kq * 4 + 2][row] = v.z; Bs[kq * 4 + 3][row] = v.w;
        }
        __syncthreads();
        #pragma unroll
        for (int kk = 0; kk < 16; kk++) {
            float4 a0 = *(const float4*)&As[kk][ty * 8];
            float4 a1 = *(const float4*)&As[kk][ty * 8 + 4];
            float4 b  = *(const float4*)&Bs[kk][tx * 4];
            float av[8] = {a0.x, a0.y, a0.z, a0.w, a1.x, a1.y, a1.z, a1.w};
            float bv[4] = {b.x, b.y, b.z, b.w};
            #pragma unroll
            for (int i = 0; i < 8; i++)
                #pragma unroll
                for (int j = 0; j < 4; j++)
                    acc[i][j] = fmaf(av[i], bv[j], acc[i][j]);
        }
        __syncthreads();
    }
    #pragma unroll
    for (int i = 0; i < 8; i++)
        *(float4*)&Cs[ty * 8 + i][tx * 4] =
            make_float4(acc[i][0], acc[i][1], acc[i][2], acc[i][3]);
    __syncthreads();
    // LN + GELU + residual; warp w handles rows w*8..w*8+7
    int w = tid >> 5, lane = tid & 31;
    for (int it = 0; it < 8; it++) {
        int r = w * 8 + it;
        int gr = m0 + r;
        float vv[4], s = 0.f, q = 0.f;
        #pragma unroll
        for (int qq = 0; qq < 4; qq++) {
            vv[qq] = Cs[r][lane + qq * 32];
            s += vv[qq]; q += vv[qq] * vv[qq];
        }
        #pragma unroll
        for (int o = 16; o; o >>= 1) {
            s += __shfl_xor_sync(0xffffffffu, s, o);
            q += __shfl_xor_sync(0xffffffffu, q, o);
        }
        float mu = s * (1.0f / DM);
        float var = q * (1.0f / DM) - mu * mu;
        float istd = rsqrtf(var + EPS_F);
        #pragma unroll
        for (int qq = 0; qq < 4; qq++) {
            int d = lane + qq * 32;
            float ln = (vv[qq] - mu) * istd * lnw[d] + lnb[d];
            g_hb[(size_t)gr * DM + d] = gelu_exact(ln) + g_h[(size_t)gr * DM + d];
        }
    }
}

// ---------------- K4: in_proj (21504x512x128) -> xc (cols<256), z ----------------
__global__ void __launch_bounds__(128) k_inproj(const float* __restrict__ W) {
    __shared__ float As[16][64], Bs[16][64];
    float acc[8][4];
    #pragma unroll
    for (int i = 0; i < 8; i++)
        #pragma unroll
        for (int j = 0; j < 4; j++) acc[i][j] = 0.f;
    int tid = threadIdx.x, tx = tid & 15, ty = tid >> 4;
    int m0 = blockIdx.x * 64, n0 = blockIdx.y * 64;
    gemm64(g_hb, DM, W + (size_t)n0 * DM, DM, m0, DM, 1 << 30, As, Bs, acc, tx, ty);
    float* dst = (n0 < 256) ? g_xc : g_z;
    int cb = (n0 < 256) ? n0 : (n0 - 256);
    #pragma unroll
    for (int i = 0; i < 8; i++) {
        int gr = m0 + ty * 8 + i;
        *(float4*)&dst[(size_t)gr * 256 + cb + tx * 4] =
            make_float4(acc[i][0], acc[i][1], acc[i][2], acc[i][3]);
    }
}

// ---------------- K5a: depthwise conv + SiLU ----------------
__global__ void k_conv(const float* __restrict__ cw, const float* __restrict__ cb) {
    int bv = blockIdx.x, c = threadIdx.x;
    const float* xp = g_xc + (size_t)bv * LSEQ * DIN;
    float* op = g_xcc + (size_t)bv * LSEQ * DIN;
    float w0 = cw[c * 4 + 0], w1 = cw[c * 4 + 1], w2 = cw[c * 4 + 2], w3 = cw[c * 4 + 3];
    float bb = cb[c];
    float xm3 = 0.f, xm2 = 0.f, xm1 = 0.f;
    for (int l = 0; l < LSEQ; l++) {
        float xv = xp[l * DIN + c];
        float t = fmaf(xm3, w0, fmaf(xm2, w1, fmaf(xm1, w2, fmaf(xv, w3, bb))));
        op[l * DIN + c] = silu_f(t);
        xm3 = xm2; xm2 = xm1; xm1 = xv;
    }
}

// ---------------- K5b: x_proj + dt_proj + softplus ----------------
__global__ void k_xproj(const float* __restrict__ xpw,
                        const float* __restrict__ dtw, const float* __restrict__ dtb) {
    int bv = blockIdx.x, tid = threadIdx.x;
    __shared__ float xs[8 * DIN];
    __shared__ float dbl[LSEQ * 40];
    const float* xcc = g_xcc + (size_t)bv * LSEQ * DIN;
    for (int lt = 0; lt < 8; lt++) {
        for (int i = tid; i < 8 * DIN; i += 256) xs[i] = xcc[lt * 8 * DIN + i];
        __syncthreads();
        int w = tid >> 5, lane = tid & 31;
        const float* xr = xs + w * DIN;
        for (int o = lane; o < 40; o += 32) {
            const float4* wp = (const float4*)(xpw + o * DIN);
            const float4* x4 = (const float4*)xr;
            float acc = 0.f;
            for (int k = 0; k < 64; k++) {
                float4 aq = x4[k]; float4 bq = wp[k];
                acc = fmaf(aq.x, bq.x, acc);
                acc = fmaf(aq.y, bq.y, acc);
                acc = fmaf(aq.z, bq.z, acc);
                acc = fmaf(aq.w, bq.w, acc);
            }
            dbl[(lt * 8 + w) * 40 + o] = acc;
        }
        __syncthreads();
    }
    int c = tid;
    float dw[8];
    #pragma unroll
    for (int r = 0; r < 8; r++) dw[r] = dtw[c * 8 + r];
    float db = dtb[c];
    float* dp = g_delta + (size_t)bv * LSEQ * DIN;
    for (int l = 0; l < LSEQ; l++) {
        float acc = db;
        #pragma unroll
        for (int r = 0; r < 8; r++) acc = fmaf(dbl[l * 40 + r], dw[r], acc);
        dp[l * DIN + c] = (acc > 20.f) ? acc : log1pf(expf(acc));
    }
    float* bc = g_BC + (size_t)bv * LSEQ * 32;
    for (int i = tid; i < LSEQ * 32; i += 256) {
        int l = i >> 5, s = i & 31;
        bc[i] = dbl[l * 40 + 8 + s];
    }
}

// ---------------- K6: selective scan ----------------
__global__ void k_scan(const float* __restrict__ A_log, const float* __restrict__ D_ssm) {
    int bv = blockIdx.x, c = threadIdx.x;
    __shared__ float bc[LSEQ * 32];
    for (int i = c; i < LSEQ * 32; i += 256) bc[i] = g_BC[(size_t)bv * LSEQ * 32 + i];
    float As[DSS];
    #pragma unroll
    for (int s = 0; s < DSS; s++) As[s] = -expf(A_log[c * DSS + s]);
    float Dv = D_ssm[c];
    float st[DSS];
    #pragma unroll
    for (int s = 0; s < DSS; s++) st[s] = 0.f;
    __syncthreads();
    size_t base = (size_t)bv * LSEQ * DIN;
    for (int l = 0; l < LSEQ; l++) {
        float d  = g_delta[base + l * DIN + c];
        float u  = g_xcc  [base + l * DIN + c];
        float zv = g_z    [base + l * DIN + c];
        float du = d * u;
        float y = 0.f;
        #pragma unroll
        for (int s = 0; s < DSS; s++) {
            float dA = __expf(d * As[s]);
            st[s] = fmaf(st[s], dA, du * bc[l * 32 + s]);
            y = fmaf(st[s], bc[l * 32 + 16 + s], y);
        }
        y = fmaf(Dv, u, y);
        y *= silu_f(zv);
        g_y[base + l * DIN + c] = y;
    }
}

// ---------------- K7: out_proj (21504x128x256) ----------------
__global__ void __launch_bounds__(128) k_outproj(const float* __restrict__ W) {
    __shared__ float As[16][64], Bs[16][64];
    float acc[8][4];
    #pragma unroll
    for (int i = 0; i < 8; i++)
        #pragma unroll
        for (int j = 0; j < 4; j++) acc[i][j] = 0.f;
    int tid = threadIdx.x, tx = tid & 15, ty = tid >> 4;
    int m0 = blockIdx.x * 64, n0 = blockIdx.y * 64;
    gemm64(g_y, DIN, W + (size_t)n0 * DIN, DIN, m0, DIN, 1 << 30, As, Bs, acc, tx, ty);
    #pragma unroll
    for (int i = 0; i < 8; i++) {
        int gr = m0 + ty * 8 + i;
        *(float4*)&g_mo[(size_t)gr * DM + n0 + tx * 4] =
            make_float4(acc[i][0], acc[i][1], acc[i][2], acc[i][3]);
    }
}

// ---------------- K8a: mlp2 split-K partials (336x192x8192, 16 splits) --------
__global__ void __launch_bounds__(128) k_mlp2p(const float* __restrict__ W) {
    __shared__ float As[16][64], Bs[16][64];
    float acc[8][4];
    #pragma unroll
    for (int i = 0; i < 8; i++)
        #pragma unroll
        for (int j = 0; j < 4; j++) acc[i][j] = 0.f;
    int tid = threadIdx.x, tx = tid & 15, ty = tid >> 4;
    int m0 = blockIdx.x * 64, n0 = blockIdx.y * 64, s = blockIdx.z;
    const float* A = g_mo + (size_t)s * 512;      // lda = 8192, k-offset s*512
    const float* B = W + (size_t)n0 * 8192 + (size_t)s * 512;
    gemm64(A, 8192, B, 8192, m0, 512, NBV, As, Bs, acc, tx, ty);
    #pragma unroll
    for (int i = 0; i < 8; i++) {
        int gr = m0 + ty * 8 + i;
        if (gr < NBV)
            *(float4*)&g_t2p[((size_t)s * NBV + gr) * 192 + n0 + tx * 4] =
                make_float4(acc[i][0], acc[i][1], acc[i][2], acc[i][3]);
    }
}

// ---------------- K8b: reduce splits + bias + GELU ----------------
__global__ void k_mlp2fin(const float* __restrict__ bias) {
    int row = blockIdx.x, col = threadIdx.x;
    float sum = 0.f;
    #pragma unroll
    for (int s = 0; s < 16; s++) sum += g_t2p[((size_t)s * NBV + row) * 192 + col];
    g_t2[(size_t)row * 192 + col] = gelu_exact(sum + bias[col]);
}

// ---------------- K9: mlp3 + denorm ----------------
__global__ void k_mlp3(const float* __restrict__ W3, const float* __restrict__ b3,
                       const float* __restrict__ rw, const float* __restrict__ rb,
                       float* __restrict__ out) {
    int bv = blockIdx.x;
    int b = bv / NVAR, v = bv % NVAR;
    int tid = threadIdx.x;
    __shared__ float ts[192];
    ts[tid] = g_t2[(size_t)bv * 192 + tid];
    __syncthreads();
    if (tid < PRED) {
        float acc = b3[tid];
        const float* w = W3 + tid * 192;
        #pragma unroll 4
        for (int j = 0; j < 192; j++) acc = fmaf(ts[j], w[j], acc);
        float val = (acc - rb[v]) / (rw[v] + 1e-10f) * g_std[bv] + g_mean[bv];
        out[((size_t)b * PRED + tid) * NVAR + v] = val;
    }
}

// ---------------- launch ----------------
extern "C" void kernel_launch(void* const* d_in, const int* in_sizes, int n_in,
                              void* d_out, int out_size) {
    const float* x         = (const float*)d_in[0];
    const float* revin_w   = (const float*)d_in[1];
    const float* revin_b   = (const float*)d_in[2];
    const float* mlp1_w    = (const float*)d_in[3];
    const float* mlp1_b    = (const float*)d_in[4];
    const float* mk_w      = (const float*)d_in[5];
    const float* mv_w      = (const float*)d_in[6];
    const float* ln_w      = (const float*)d_in[7];
    const float* ln_b      = (const float*)d_in[8];
    const float* in_proj_w = (const float*)d_in[9];
    const float* conv_w    = (const float*)d_in[10];
    const float* conv_b    = (const float*)d_in[11];
    const float* x_proj_w  = (const float*)d_in[12];
    const float* dt_proj_w = (const float*)d_in[13];
    const float* dt_proj_b = (const float*)d_in[14];
    const float* A_log     = (const float*)d_in[15];
    const float* D_ssm     = (const float*)d_in[16];
    const float* out_proj_w= (const float*)d_in[17];
    const float* mlp2_w    = (const float*)d_in[18];
    const float* mlp2_b    = (const float*)d_in[19];
    const float* mlp3_w    = (const float*)d_in[20];
    const float* mlp3_b    = (const float*)d_in[21];
    float* out = (float*)d_out;

    k_revin  <<<NBV, 512>>>(x, revin_w, revin_b);
    k_mlp1   <<<NBV, 128>>>(mlp1_w, mlp1_b);
    k_scores <<<dim3(MROWS / 64, SEA / 64), 128>>>(mk_w);
    k_softmax<<<MROWS / 4, 128>>>();
    k_av     <<<MROWS / 64, 256>>>(mv_w, ln_w, ln_b);
    k_inproj <<<dim3(MROWS / 64, 512 / 64), 128>>>(in_proj_w);
    k_conv   <<<NBV, 256>>>(conv_w, conv_b);
    k_xproj  <<<NBV, 256>>>(x_proj_w, dt_proj_w, dt_proj_b);
    k_scan   <<<NBV, 256>>>(A_log, D_ssm);
    k_outproj<<<dim3(MROWS / 64, 2), 128>>>(out_proj_w);
    k_mlp2p  <<<dim3(6, 3, 16), 128>>>(mlp2_w);
    k_mlp2fin<<<NBV, 192>>>(mlp2_b);
    k_mlp3   <<<NBV, 192>>>(mlp3_w, mlp3_b, revin_w, revin_b, out);
}

// round 5
// speedup vs baseline: 4.6325x; 1.1935x over previous
#include <cuda_runtime.h>
#include <math.h>
#include <stdint.h>

#define NBV   336      // B*NV
#define NVAR  21
#define TT    512
#define TP    520
#define PNUM  64
#define DM    128
#define SEA   512
#define DIN   256
#define DSS   16
#define LSEQ  64
#define PRED  96
#define EPS_F 1e-5f
#define MROWS (NBV * PNUM)   // 21504 global rows
#define LDS_P 20             // smem tile row pitch (floats), conflict-free

// ---------------- scratch ----------------
__device__ float g_xn[NBV * TP];
__device__ float g_mean[NBV];
__device__ float g_std[NBV];
__device__ float g_h [MROWS * DM];
__device__ float g_hb[MROWS * DM];
__device__ float g_ps[MROWS * SEA];          // 44MB attention scores
__device__ float g_xc  [MROWS * DIN];
__device__ float g_z   [MROWS * DIN];
__device__ float g_xcc [MROWS * DIN];
__device__ float g_delta[MROWS * DIN];
__device__ float g_BC  [NBV * LSEQ * 32];
__device__ float g_y   [MROWS * DIN];
__device__ float g_mo  [MROWS * DM];
__device__ float g_t2p [16 * NBV * 192];
__device__ float g_t2  [NBV * 192];

__device__ __forceinline__ float gelu_exact(float x) {
    return 0.5f * x * (1.0f + erff(x * 0.70710678118654752f));
}
__device__ __forceinline__ float silu_f(float x) {
    return x / (1.0f + __expf(-x));
}
__device__ __forceinline__ uint32_t f2tf(float x) {
    uint32_t r;
    asm("cvt.rna.tf32.f32 %0, %1;" : "=r"(r) : "f"(x));
    return r;
}
__device__ __forceinline__ void mma_tf32(float c[4], const uint32_t a[4], const uint32_t b[2]) {
    asm volatile("mma.sync.aligned.m16n8k8.row.col.f32.tf32.tf32.f32 "
        "{%0,%1,%2,%3},{%4,%5,%6,%7},{%8,%9},{%0,%1,%2,%3};"
        : "+f"(c[0]), "+f"(c[1]), "+f"(c[2]), "+f"(c[3])
        : "r"(a[0]), "r"(a[1]), "r"(a[2]), "r"(a[3]), "r"(b[0]), "r"(b[1]));
}

// ---------------- tf32 64x64 tile core (NT: C = A[M,K] * B[N,K]^T) ----------
// 128 threads = 4 warps (warpM = wid&1, warpN = wid>>1), warp tile 32x32.
__device__ __forceinline__ void gemm_tf32_64(
    const float* __restrict__ A, int lda,
    const float* __restrict__ Bn, int ldb,   // pre-offset to n0
    int m0, int K, int Mmax,
    uint32_t As[64][LDS_P], uint32_t Bs[64][LDS_P],
    float acc[2][4][4])
{
    int tid = threadIdx.x;
    int lane = tid & 31, wid = tid >> 5;
    int warpM = wid & 1, warpN = wid >> 1;
    int g = lane >> 2, tg = lane & 3;
    for (int k0 = 0; k0 < K; k0 += 16) {
        #pragma unroll
        for (int u = 0; u < 2; u++) {
            int f = tid * 2 + u, row = f >> 2, kq = f & 3;
            float4 v = make_float4(0.f, 0.f, 0.f, 0.f);
            int gr = m0 + row;
            if (gr < Mmax) v = *(const float4*)(A + (size_t)gr * lda + k0 + kq * 4);
            uint32_t* d = &As[row][kq * 4];
            d[0] = f2tf(v.x); d[1] = f2tf(v.y); d[2] = f2tf(v.z); d[3] = f2tf(v.w);
        }
        #pragma unroll
        for (int u = 0; u < 2; u++) {
            int f = tid * 2 + u, row = f >> 2, kq = f & 3;
            float4 v = *(const float4*)(Bn + (size_t)row * ldb + k0 + kq * 4);
            uint32_t* d = &Bs[row][kq * 4];
            d[0] = f2tf(v.x); d[1] = f2tf(v.y); d[2] = f2tf(v.z); d[3] = f2tf(v.w);
        }
        __syncthreads();
        #pragma unroll
        for (int ks = 0; ks < 2; ks++) {
            int kk = ks * 8;
            uint32_t a[2][4], b[4][2];
            #pragma unroll
            for (int mi = 0; mi < 2; mi++) {
                int mr = warpM * 32 + mi * 16;
                a[mi][0] = As[mr + g][kk + tg];
                a[mi][1] = As[mr + g + 8][kk + tg];
                a[mi][2] = As[mr + g][kk + tg + 4];
                a[mi][3] = As[mr + g + 8][kk + tg + 4];
            }
            #pragma unroll
            for (int ni = 0; ni < 4; ni++) {
                int nr = warpN * 32 + ni * 8 + g;
                b[ni][0] = Bs[nr][kk + tg];
                b[ni][1] = Bs[nr][kk + tg + 4];
            }
            #pragma unroll
            for (int mi = 0; mi < 2; mi++)
                #pragma unroll
                for (int ni = 0; ni < 4; ni++)
                    mma_tf32(acc[mi][ni], a[mi], b[ni]);
        }
        __syncthreads();
    }
}

// ---------------- K1: RevIN ----------------
__global__ void k_revin(const float* __restrict__ x,
                        const float* __restrict__ rw, const float* __restrict__ rb) {
    int bv = blockIdx.x;
    int b = bv / NVAR, v = bv % NVAR;
    int t = threadIdx.x;
    float val = x[(size_t)(b * TT + t) * NVAR + v];
    __shared__ float s1[16], s2[16];
    float a = val, q = val * val;
    #pragma unroll
    for (int o = 16; o; o >>= 1) {
        a += __shfl_down_sync(0xffffffffu, a, o);
        q += __shfl_down_sync(0xffffffffu, q, o);
    }
    if ((t & 31) == 0) { s1[t >> 5] = a; s2[t >> 5] = q; }
    __syncthreads();
    __shared__ float mb[2];
    if (t < 32) {
        float a2 = (t < 16) ? s1[t] : 0.f;
        float q2 = (t < 16) ? s2[t] : 0.f;
        #pragma unroll
        for (int o = 8; o; o >>= 1) {
            a2 += __shfl_down_sync(0xffffffffu, a2, o);
            q2 += __shfl_down_sync(0xffffffffu, q2, o);
        }
        if (t == 0) {
            float mean = a2 * (1.0f / TT);
            float var  = q2 * (1.0f / TT) - mean * mean;
            float sd   = sqrtf(var + EPS_F);
            mb[0] = mean; mb[1] = sd;
            g_mean[bv] = mean; g_std[bv] = sd;
        }
    }
    __syncthreads();
    float xnv = (val - mb[0]) / mb[1] * rw[v] + rb[v];
    g_xn[bv * TP + t] = xnv;
    if (t == TT - 1) {
        #pragma unroll
        for (int i = 0; i < 8; i++) g_xn[bv * TP + TT + i] = xnv;
    }
}

// ---------------- K2: mlp1 ----------------
__global__ void k_mlp1(const float* __restrict__ w, const float* __restrict__ bias) {
    int bv = blockIdx.x;
    int d = threadIdx.x;
    __shared__ float xs[TP];
    for (int i = d; i < TP; i += 128) xs[i] = g_xn[bv * TP + i];
    float wr[16];
    #pragma unroll
    for (int s = 0; s < 16; s++) wr[s] = w[d * 16 + s];
    float bb = bias[d];
    __syncthreads();
    float* hp = g_h + (size_t)bv * PNUM * DM;
    #pragma unroll 4
    for (int p = 0; p < PNUM; p++) {
        float acc = bb;
        const float* xp = xs + p * 8;
        #pragma unroll
        for (int s = 0; s < 16; s++) acc = fmaf(xp[s], wr[s], acc);
        hp[p * DM + d] = acc;
    }
}

// ---------------- K3a: scores = h @ mk^T (21504x512x128) ----------------
__global__ void __launch_bounds__(128) k_scores(const float* __restrict__ mk) {
    __shared__ uint32_t As[64][LDS_P], Bs[64][LDS_P];
    float acc[2][4][4];
    #pragma unroll
    for (int i = 0; i < 2; i++)
        #pragma unroll
        for (int j = 0; j < 4; j++)
            #pragma unroll
            for (int c = 0; c < 4; c++) acc[i][j][c] = 0.f;
    int m0 = blockIdx.x * 64, n0 = blockIdx.y * 64;
    gemm_tf32_64(g_h, DM, mk + (size_t)n0 * DM, DM, m0, DM, 1 << 30, As, Bs, acc);
    int lane = threadIdx.x & 31, wid = threadIdx.x >> 5;
    int warpM = wid & 1, warpN = wid >> 1;
    int g = lane >> 2, tg = lane & 3;
    #pragma unroll
    for (int mi = 0; mi < 2; mi++)
        #pragma unroll
        for (int ni = 0; ni < 4; ni++) {
            int row = m0 + warpM * 32 + mi * 16 + g;
            int col = n0 + warpN * 32 + ni * 8 + tg * 2;
            *(float2*)&g_ps[(size_t)row * SEA + col] = make_float2(acc[mi][ni][0], acc[mi][ni][1]);
            *(float2*)&g_ps[(size_t)(row + 8) * SEA + col] = make_float2(acc[mi][ni][2], acc[mi][ni][3]);
        }
}

// ---------------- K3b: row softmax over 512 ----------------
__global__ void k_softmax() {
    int tid = threadIdx.x, lane = tid & 31, w = tid >> 5;
    int row = blockIdx.x * 4 + w;
    float4* base = (float4*)(g_ps + (size_t)row * SEA);
    float4 v[4];
    float mx = -1e30f;
    #pragma unroll
    for (int q = 0; q < 4; q++) {
        v[q] = base[q * 32 + lane];
        mx = fmaxf(mx, fmaxf(fmaxf(v[q].x, v[q].y), fmaxf(v[q].z, v[q].w)));
    }
    #pragma unroll
    for (int o = 16; o; o >>= 1) mx = fmaxf(mx, __shfl_xor_sync(0xffffffffu, mx, o));
    float sum = 0.f;
    #pragma unroll
    for (int q = 0; q < 4; q++) {
        v[q].x = __expf(v[q].x - mx); v[q].y = __expf(v[q].y - mx);
        v[q].z = __expf(v[q].z - mx); v[q].w = __expf(v[q].w - mx);
        sum += v[q].x + v[q].y + v[q].z + v[q].w;
    }
    #pragma unroll
    for (int o = 16; o; o >>= 1) sum += __shfl_xor_sync(0xffffffffu, sum, o);
    float inv = 1.0f / sum;
    #pragma unroll
    for (int q = 0; q < 4; q++) {
        v[q].x *= inv; v[q].y *= inv; v[q].z *= inv; v[q].w *= inv;
        base[q * 32 + lane] = v[q];
    }
}

// ---------------- K3c: AV = P @ mv^T (21504x128x512), fused LN+GELU+residual ----
// 256 threads = 8 warps (warpM = wid&1, warpN = wid>>1 in 0..3), tile 64x128.
__global__ void __launch_bounds__(256) k_av(const float* __restrict__ mv,
                     const float* __restrict__ lnw, const float* __restrict__ lnb) {
    __shared__ uint32_t As[64][LDS_P];
    __shared__ uint32_t Bs[128][LDS_P];
    __shared__ float Cs[64][128];
    int tid = threadIdx.x;
    int lane = tid & 31, wid = tid >> 5;
    int warpM = wid & 1, warpN = wid >> 1;
    int g = lane >> 2, tg = lane & 3;
    int m0 = blockIdx.x * 64;
    float acc[2][4][4];
    #pragma unroll
    for (int i = 0; i < 2; i++)
        #pragma unroll
        for (int j = 0; j < 4; j++)
            #pragma unroll
            for (int c = 0; c < 4; c++) acc[i][j][c] = 0.f;
    for (int k0 = 0; k0 < SEA; k0 += 16) {
        {
            int f = tid, row = f >> 2, kq = f & 3;
            float4 v = *(const float4*)(g_ps + (size_t)(m0 + row) * SEA + k0 + kq * 4);
            uint32_t* d = &As[row][kq * 4];
            d[0] = f2tf(v.x); d[1] = f2tf(v.y); d[2] = f2tf(v.z); d[3] = f2tf(v.w);
        }
        #pragma unroll
        for (int u = 0; u < 2; u++) {
            int f = tid * 2 + u, row = f >> 2, kq = f & 3;
            float4 v = *(const float4*)(mv + (size_t)row * SEA + k0 + kq * 4);
            uint32_t* d = &Bs[row][kq * 4];
            d[0] = f2tf(v.x); d[1] = f2tf(v.y); d[2] = f2tf(v.z); d[3] = f2tf(v.w);
        }
        __syncthreads();
        #pragma unroll
        for (int ks = 0; ks < 2; ks++) {
            int kk = ks * 8;
            uint32_t a[2][4], b[4][2];
            #pragma unroll
            for (int mi = 0; mi < 2; mi++) {
                int mr = warpM * 32 + mi * 16;
                a[mi][0] = As[mr + g][kk + tg];
                a[mi][1] = As[mr + g + 8][kk + tg];
                a[mi][2] = As[mr + g][kk + tg + 4];
                a[mi][3] = As[mr + g + 8][kk + tg + 4];
            }
            #pragma unroll
            for (int ni = 0; ni < 4; ni++) {
                int nr = warpN * 32 + ni * 8 + g;
                b[ni][0] = Bs[nr][kk + tg];
                b[ni][1] = Bs[nr][kk + tg + 4];
            }
            #pragma unroll
            for (int mi = 0; mi < 2; mi++)
                #pragma unroll
                for (int ni = 0; ni < 4; ni++)
                    mma_tf32(acc[mi][ni], a[mi], b[ni]);
        }
        __syncthreads();
    }
    #pragma unroll
    for (int mi = 0; mi < 2; mi++)
        #pragma unroll
        for (int ni = 0; ni < 4; ni++) {
            int row = warpM * 32 + mi * 16 + g;
            int col = warpN * 32 + ni * 8 + tg * 2;
            *(float2*)&Cs[row][col] = make_float2(acc[mi][ni][0], acc[mi][ni][1]);
            *(float2*)&Cs[row + 8][col] = make_float2(acc[mi][ni][2], acc[mi][ni][3]);
        }
    __syncthreads();
    // LN + GELU + residual; warp w handles rows w*8..w*8+7
    int w = tid >> 5;
    for (int it = 0; it < 8; it++) {
        int r = w * 8 + it;
        int gr = m0 + r;
        float vv[4], s = 0.f, q = 0.f;
        #pragma unroll
        for (int qq = 0; qq < 4; qq++) {
            vv[qq] = Cs[r][lane + qq * 32];
            s += vv[qq]; q += vv[qq] * vv[qq];
        }
        #pragma unroll
        for (int o = 16; o; o >>= 1) {
            s += __shfl_xor_sync(0xffffffffu, s, o);
            q += __shfl_xor_sync(0xffffffffu, q, o);
        }
        float mu = s * (1.0f / DM);
        float var = q * (1.0f / DM) - mu * mu;
        float istd = rsqrtf(var + EPS_F);
        #pragma unroll
        for (int qq = 0; qq < 4; qq++) {
            int d = lane + qq * 32;
            float ln = (vv[qq] - mu) * istd * lnw[d] + lnb[d];
            g_hb[(size_t)gr * DM + d] = gelu_exact(ln) + g_h[(size_t)gr * DM + d];
        }
    }
}

// ---------------- K4: in_proj (21504x512x128) -> xc (cols<256), z ----------------
__global__ void __launch_bounds__(128) k_inproj(const float* __restrict__ W) {
    __shared__ uint32_t As[64][LDS_P], Bs[64][LDS_P];
    float acc[2][4][4];
    #pragma unroll
    for (int i = 0; i < 2; i++)
        #pragma unroll
        for (int j = 0; j < 4; j++)
            #pragma unroll
            for (int c = 0; c < 4; c++) acc[i][j][c] = 0.f;
    int m0 = blockIdx.x * 64, n0 = blockIdx.y * 64;
    gemm_tf32_64(g_hb, DM, W + (size_t)n0 * DM, DM, m0, DM, 1 << 30, As, Bs, acc);
    float* dst = (n0 < 256) ? g_xc : g_z;
    int cb = (n0 < 256) ? n0 : (n0 - 256);
    int lane = threadIdx.x & 31, wid = threadIdx.x >> 5;
    int warpM = wid & 1, warpN = wid >> 1;
    int g = lane >> 2, tg = lane & 3;
    #pragma unroll
    for (int mi = 0; mi < 2; mi++)
        #pragma unroll
        for (int ni = 0; ni < 4; ni++) {
            int row = m0 + warpM * 32 + mi * 16 + g;
            int col = cb + warpN * 32 + ni * 8 + tg * 2;
            *(float2*)&dst[(size_t)row * 256 + col] = make_float2(acc[mi][ni][0], acc[mi][ni][1]);
            *(float2*)&dst[(size_t)(row + 8) * 256 + col] = make_float2(acc[mi][ni][2], acc[mi][ni][3]);
        }
}

// ---------------- K5a: depthwise conv + SiLU ----------------
__global__ void k_conv(const float* __restrict__ cw, const float* __restrict__ cb) {
    int bv = blockIdx.x, c = threadIdx.x;
    const float* xp = g_xc + (size_t)bv * LSEQ * DIN;
    float* op = g_xcc + (size_t)bv * LSEQ * DIN;
    float w0 = cw[c * 4 + 0], w1 = cw[c * 4 + 1], w2 = cw[c * 4 + 2], w3 = cw[c * 4 + 3];
    float bb = cb[c];
    float xm3 = 0.f, xm2 = 0.f, xm1 = 0.f;
    for (int l = 0; l < LSEQ; l++) {
        float xv = xp[l * DIN + c];
        float t = fmaf(xm3, w0, fmaf(xm2, w1, fmaf(xm1, w2, fmaf(xv, w3, bb))));
        op[l * DIN + c] = silu_f(t);
        xm3 = xm2; xm2 = xm1; xm1 = xv;
    }
}

// ---------------- K5b: x_proj + dt_proj + softplus ----------------
__global__ void k_xproj(const float* __restrict__ xpw,
                        const float* __restrict__ dtw, const float* __restrict__ dtb) {
    int bv = blockIdx.x, tid = threadIdx.x;
    __shared__ float xs[8 * DIN];
    __shared__ float dbl[LSEQ * 40];
    const float* xcc = g_xcc + (size_t)bv * LSEQ * DIN;
    for (int lt = 0; lt < 8; lt++) {
        for (int i = tid; i < 8 * DIN; i += 256) xs[i] = xcc[lt * 8 * DIN + i];
        __syncthreads();
        int w = tid >> 5, lane = tid & 31;
        const float* xr = xs + w * DIN;
        for (int o = lane; o < 40; o += 32) {
            const float4* wp = (const float4*)(xpw + o * DIN);
            const float4* x4 = (const float4*)xr;
            float acc = 0.f;
            for (int k = 0; k < 64; k++) {
                float4 aq = x4[k]; float4 bq = wp[k];
                acc = fmaf(aq.x, bq.x, acc);
                acc = fmaf(aq.y, bq.y, acc);
                acc = fmaf(aq.z, bq.z, acc);
                acc = fmaf(aq.w, bq.w, acc);
            }
            dbl[(lt * 8 + w) * 40 + o] = acc;
        }
        __syncthreads();
    }
    int c = tid;
    float dw[8];
    #pragma unroll
    for (int r = 0; r < 8; r++) dw[r] = dtw[c * 8 + r];
    float db = dtb[c];
    float* dp = g_delta + (size_t)bv * LSEQ * DIN;
    for (int l = 0; l < LSEQ; l++) {
        float acc = db;
        #pragma unroll
        for (int r = 0; r < 8; r++) acc = fmaf(dbl[l * 40 + r], dw[r], acc);
        dp[l * DIN + c] = (acc > 20.f) ? acc : log1pf(expf(acc));
    }
    float* bc = g_BC + (size_t)bv * LSEQ * 32;
    for (int i = tid; i < LSEQ * 32; i += 256) {
        int l = i >> 5, s = i & 31;
        bc[i] = dbl[l * 40 + 8 + s];
    }
}

// ---------------- K6: selective scan ----------------
__global__ void k_scan(const float* __restrict__ A_log, const float* __restrict__ D_ssm) {
    int bv = blockIdx.x, c = threadIdx.x;
    __shared__ float bc[LSEQ * 32];
    for (int i = c; i < LSEQ * 32; i += 256) bc[i] = g_BC[(size_t)bv * LSEQ * 32 + i];
    float As[DSS];
    #pragma unroll
    for (int s = 0; s < DSS; s++) As[s] = -expf(A_log[c * DSS + s]);
    float Dv = D_ssm[c];
    float st[DSS];
    #pragma unroll
    for (int s = 0; s < DSS; s++) st[s] = 0.f;
    __syncthreads();
    size_t base = (size_t)bv * LSEQ * DIN;
    for (int l = 0; l < LSEQ; l++) {
        float d  = g_delta[base + l * DIN + c];
        float u  = g_xcc  [base + l * DIN + c];
        float zv = g_z    [base + l * DIN + c];
        float du = d * u;
        float y = 0.f;
        #pragma unroll
        for (int s = 0; s < DSS; s++) {
            float dA = __expf(d * As[s]);
            st[s] = fmaf(st[s], dA, du * bc[l * 32 + s]);
            y = fmaf(st[s], bc[l * 32 + 16 + s], y);
        }
        y = fmaf(Dv, u, y);
        y *= silu_f(zv);
        g_y[base + l * DIN + c] = y;
    }
}

// ---------------- K7: out_proj (21504x128x256) ----------------
__global__ void __launch_bounds__(128) k_outproj(const float* __restrict__ W) {
    __shared__ uint32_t As[64][LDS_P], Bs[64][LDS_P];
    float acc[2][4][4];
    #pragma unroll
    for (int i = 0; i < 2; i++)
        #pragma unroll
        for (int j = 0; j < 4; j++)
            #pragma unroll
            for (int c = 0; c < 4; c++) acc[i][j][c] = 0.f;
    int m0 = blockIdx.x * 64, n0 = blockIdx.y * 64;
    gemm_tf32_64(g_y, DIN, W + (size_t)n0 * DIN, DIN, m0, DIN, 1 << 30, As, Bs, acc);
    int lane = threadIdx.x & 31, wid = threadIdx.x >> 5;
    int warpM = wid & 1, warpN = wid >> 1;
    int g = lane >> 2, tg = lane & 3;
    #pragma unroll
    for (int mi = 0; mi < 2; mi++)
        #pragma unroll
        for (int ni = 0; ni < 4; ni++) {
            int row = m0 + warpM * 32 + mi * 16 + g;
            int col = n0 + warpN * 32 + ni * 8 + tg * 2;
            *(float2*)&g_mo[(size_t)row * DM + col] = make_float2(acc[mi][ni][0], acc[mi][ni][1]);
            *(float2*)&g_mo[(size_t)(row + 8) * DM + col] = make_float2(acc[mi][ni][2], acc[mi][ni][3]);
        }
}

// ---------------- K8a: mlp2 split-K partials (336x192x8192, 16 splits) --------
__global__ void __launch_bounds__(128) k_mlp2p(const float* __restrict__ W) {
    __shared__ uint32_t As[64][LDS_P], Bs[64][LDS_P];
    float acc[2][4][4];
    #pragma unroll
    for (int i = 0; i < 2; i++)
        #pragma unroll
        for (int j = 0; j < 4; j++)
            #pragma unroll
            for (int c = 0; c < 4; c++) acc[i][j][c] = 0.f;
    int m0 = blockIdx.x * 64, n0 = blockIdx.y * 64, s = blockIdx.z;
    const float* A = g_mo + (size_t)s * 512;
    const float* B = W + (size_t)n0 * 8192 + (size_t)s * 512;
    gemm_tf32_64(A, 8192, B, 8192, m0, 512, NBV, As, Bs, acc);
    int lane = threadIdx.x & 31, wid = threadIdx.x >> 5;
    int warpM = wid & 1, warpN = wid >> 1;
    int g = lane >> 2, tg = lane & 3;
    #pragma unroll
    for (int mi = 0; mi < 2; mi++)
        #pragma unroll
        for (int ni = 0; ni < 4; ni++) {
            int row = m0 + warpM * 32 + mi * 16 + g;
            int col = n0 + warpN * 32 + ni * 8 + tg * 2;
            if (row < NBV)
                *(float2*)&g_t2p[((size_t)s * NBV + row) * 192 + col] =
                    make_float2(acc[mi][ni][0], acc[mi][ni][1]);
            if (row + 8 < NBV)
                *(float2*)&g_t2p[((size_t)s * NBV + row + 8) * 192 + col] =
                    make_float2(acc[mi][ni][2], acc[mi][ni][3]);
        }
}

// ---------------- K8b: reduce splits + bias + GELU ----------------
__global__ void k_mlp2fin(const float* __restrict__ bias) {
    int row = blockIdx.x, col = threadIdx.x;
    float sum = 0.f;
    #pragma unroll
    for (int s = 0; s < 16; s++) sum += g_t2p[((size_t)s * NBV + row) * 192 + col];
    g_t2[(size_t)row * 192 + col] = gelu_exact(sum + bias[col]);
}

// ---------------- K9: mlp3 + denorm ----------------
__global__ void k_mlp3(const float* __restrict__ W3, const float* __restrict__ b3,
                       const float* __restrict__ rw, const float* __restrict__ rb,
                       float* __restrict__ out) {
    int bv = blockIdx.x;
    int b = bv / NVAR, v = bv % NVAR;
    int tid = threadIdx.x;
    __shared__ float ts[192];
    ts[tid] = g_t2[(size_t)bv * 192 + tid];
    __syncthreads();
    if (tid < PRED) {
        float acc = b3[tid];
        const float* w = W3 + tid * 192;
        #pragma unroll 4
        for (int j = 0; j < 192; j++) acc = fmaf(ts[j], w[j], acc);
        float val = (acc - rb[v]) / (rw[v] + 1e-10f) * g_std[bv] + g_mean[bv];
        out[((size_t)b * PRED + tid) * NVAR + v] = val;
    }
}

// ---------------- launch ----------------
extern "C" void kernel_launch(void* const* d_in, const int* in_sizes, int n_in,
                              void* d_out, int out_size) {
    const float* x         = (const float*)d_in[0];
    const float* revin_w   = (const float*)d_in[1];
    const float* revin_b   = (const float*)d_in[2];
    const float* mlp1_w    = (const float*)d_in[3];
    const float* mlp1_b    = (const float*)d_in[4];
    const float* mk_w      = (const float*)d_in[5];
    const float* mv_w      = (const float*)d_in[6];
    const float* ln_w      = (const float*)d_in[7];
    const float* ln_b      = (const float*)d_in[8];
    const float* in_proj_w = (const float*)d_in[9];
    const float* conv_w    = (const float*)d_in[10];
    const float* conv_b    = (const float*)d_in[11];
    const float* x_proj_w  = (const float*)d_in[12];
    const float* dt_proj_w = (const float*)d_in[13];
    const float* dt_proj_b = (const float*)d_in[14];
    const float* A_log     = (const float*)d_in[15];
    const float* D_ssm     = (const float*)d_in[16];
    const float* out_proj_w= (const float*)d_in[17];
    const float* mlp2_w    = (const float*)d_in[18];
    const float* mlp2_b    = (const float*)d_in[19];
    const float* mlp3_w    = (const float*)d_in[20];
    const float* mlp3_b    = (const float*)d_in[21];
    float* out = (float*)d_out;

    k_revin  <<<NBV, 512>>>(x, revin_w, revin_b);
    k_mlp1   <<<NBV, 128>>>(mlp1_w, mlp1_b);
    k_scores <<<dim3(MROWS / 64, SEA / 64), 128>>>(mk_w);
    k_softmax<<<MROWS / 4, 128>>>();
    k_av     <<<MROWS / 64, 256>>>(mv_w, ln_w, ln_b);
    k_inproj <<<dim3(MROWS / 64, 512 / 64), 128>>>(in_proj_w);
    k_conv   <<<NBV, 256>>>(conv_w, conv_b);
    k_xproj  <<<NBV, 256>>>(x_proj_w, dt_proj_w, dt_proj_b);
    k_scan   <<<NBV, 256>>>(A_log, D_ssm);
    k_outproj<<<dim3(MROWS / 64, 2), 128>>>(out_proj_w);
    k_mlp2p  <<<dim3(6, 3, 16), 128>>>(mlp2_w);
    k_mlp2fin<<<NBV, 192>>>(mlp2_b);
    k_mlp3   <<<NBV, 192>>>(mlp3_w, mlp3_b, revin_w, revin_b, out);
}

// round 6
// speedup vs baseline: 9.6898x; 2.0917x over previous
#include <cuda_runtime.h>
#include <cuda_bf16.h>
#include <math.h>
#include <stdint.h>

#define NBV   336
#define NVAR  21
#define TT    512
#define TP    520
#define PNUM  64
#define DM    128
#define SEA   512
#define DIN   256
#define DSS   16
#define LSEQ  64
#define PRED  96
#define EPS_F 1e-5f
#define MROWS (NBV * PNUM)   // 21504
#define WP    20             // smem word pitch (uint32), conflict-free

// ---------------- scratch ----------------
__device__ float    g_xn[NBV * TP];
__device__ float    g_mean[NBV];
__device__ float    g_std[NBV];
__device__ float    g_h  [MROWS * DM];
__device__ float    g_hb [MROWS * DM];
__device__ uint32_t g_psb[MROWS * 256];      // scores/P as bf16x2 words (22MB)
__device__ float    g_z   [MROWS * DIN];
__device__ float    g_xcc [MROWS * DIN];
__device__ float    g_dbl [MROWS * 40];
__device__ float    g_y   [MROWS * DIN];
__device__ float    g_mo  [MROWS * DM];
__device__ float    g_t2p [16 * NBV * 192];

__device__ __forceinline__ float gelu_exact(float x) {
    return 0.5f * x * (1.0f + erff(x * 0.70710678118654752f));
}
__device__ __forceinline__ float silu_f(float x) {
    return x / (1.0f + __expf(-x));
}
__device__ __forceinline__ uint32_t pack_bf(float a, float b) {
    __nv_bfloat162 t = __floats2bfloat162_rn(a, b);
    return *(uint32_t*)&t;
}
__device__ __forceinline__ void mma_bf16(float c[4], const uint32_t a[4], const uint32_t b[2]) {
    asm volatile("mma.sync.aligned.m16n8k16.row.col.f32.bf16.bf16.f32 "
        "{%0,%1,%2,%3},{%4,%5,%6,%7},{%8,%9},{%0,%1,%2,%3};"
        : "+f"(c[0]), "+f"(c[1]), "+f"(c[2]), "+f"(c[3])
        : "r"(a[0]), "r"(a[1]), "r"(a[2]), "r"(a[3]), "r"(b[0]), "r"(b[1]));
}

// ---------- bf16 64x64 tile core (NT: C = A[M,K] * B[N,K]^T), 128 threads ----
// K-step 32 (16 packed words). Fragments: m16n8k16.
__device__ __forceinline__ void gemm_bf16_64(
    const float* __restrict__ A, int lda,
    const float* __restrict__ Bn, int ldb, int Nvalid,
    int m0, int K, int Mmax,
    uint32_t As[64][WP], uint32_t Bs[64][WP],
    float acc[2][4][4])
{
    int tid = threadIdx.x;
    int lane = tid & 31, wid = tid >> 5;
    int warpM = wid & 1, warpN = wid >> 1;
    int g = lane >> 2, tg = lane & 3;
    for (int k0 = 0; k0 < K; k0 += 32) {
        #pragma unroll
        for (int u = 0; u < 4; u++) {
            int f = tid * 4 + u, row = f >> 3, q = f & 7;
            float4 v = make_float4(0.f, 0.f, 0.f, 0.f);
            int gr = m0 + row;
            if (gr < Mmax) v = *(const float4*)(A + (size_t)gr * lda + k0 + q * 4);
            *(uint2*)&As[row][q * 2] = make_uint2(pack_bf(v.x, v.y), pack_bf(v.z, v.w));
        }
        #pragma unroll
        for (int u = 0; u < 4; u++) {
            int f = tid * 4 + u, row = f >> 3, q = f & 7;
            float4 v = make_float4(0.f, 0.f, 0.f, 0.f);
            if (row < Nvalid) v = *(const float4*)(Bn + (size_t)row * ldb + k0 + q * 4);
            *(uint2*)&Bs[row][q * 2] = make_uint2(pack_bf(v.x, v.y), pack_bf(v.z, v.w));
        }
        __syncthreads();
        #pragma unroll
        for (int ks = 0; ks < 2; ks++) {
            int kk = ks * 8;
            uint32_t a[2][4], b[4][2];
            #pragma unroll
            for (int mi = 0; mi < 2; mi++) {
                int mr = warpM * 32 + mi * 16;
                a[mi][0] = As[mr + g][kk + tg];
                a[mi][1] = As[mr + g + 8][kk + tg];
                a[mi][2] = As[mr + g][kk + tg + 4];
                a[mi][3] = As[mr + g + 8][kk + tg + 4];
            }
            #pragma unroll
            for (int ni = 0; ni < 4; ni++) {
                int nr = warpN * 32 + ni * 8 + g;
                b[ni][0] = Bs[nr][kk + tg];
                b[ni][1] = Bs[nr][kk + tg + 4];
            }
            #pragma unroll
            for (int mi = 0; mi < 2; mi++)
                #pragma unroll
                for (int ni = 0; ni < 4; ni++)
                    mma_bf16(acc[mi][ni], a[mi], b[ni]);
        }
        __syncthreads();
    }
}

// ---------------- K1: RevIN ----------------
__global__ void k_revin(const float* __restrict__ x,
                        const float* __restrict__ rw, const float* __restrict__ rb) {
    int bv = blockIdx.x;
    int b = bv / NVAR, v = bv % NVAR;
    int t = threadIdx.x;
    float val = x[(size_t)(b * TT + t) * NVAR + v];
    __shared__ float s1[16], s2[16];
    float a = val, q = val * val;
    #pragma unroll
    for (int o = 16; o; o >>= 1) {
        a += __shfl_down_sync(0xffffffffu, a, o);
        q += __shfl_down_sync(0xffffffffu, q, o);
    }
    if ((t & 31) == 0) { s1[t >> 5] = a; s2[t >> 5] = q; }
    __syncthreads();
    __shared__ float mb[2];
    if (t < 32) {
        float a2 = (t < 16) ? s1[t] : 0.f;
        float q2 = (t < 16) ? s2[t] : 0.f;
        #pragma unroll
        for (int o = 8; o; o >>= 1) {
            a2 += __shfl_down_sync(0xffffffffu, a2, o);
            q2 += __shfl_down_sync(0xffffffffu, q2, o);
        }
        if (t == 0) {
            float mean = a2 * (1.0f / TT);
            float var  = q2 * (1.0f / TT) - mean * mean;
            float sd   = sqrtf(var + EPS_F);
            mb[0] = mean; mb[1] = sd;
            g_mean[bv] = mean; g_std[bv] = sd;
        }
    }
    __syncthreads();
    float xnv = (val - mb[0]) / mb[1] * rw[v] + rb[v];
    g_xn[bv * TP + t] = xnv;
    if (t == TT - 1) {
        #pragma unroll
        for (int i = 0; i < 8; i++) g_xn[bv * TP + TT + i] = xnv;
    }
}

// ---------------- K2: mlp1 ----------------
__global__ void k_mlp1(const float* __restrict__ w, const float* __restrict__ bias) {
    int bv = blockIdx.x;
    int d = threadIdx.x;
    __shared__ float xs[TP];
    for (int i = d; i < TP; i += 128) xs[i] = g_xn[bv * TP + i];
    float wr[16];
    #pragma unroll
    for (int s = 0; s < 16; s++) wr[s] = w[d * 16 + s];
    float bb = bias[d];
    __syncthreads();
    float* hp = g_h + (size_t)bv * PNUM * DM;
    #pragma unroll 4
    for (int p = 0; p < PNUM; p++) {
        float acc = bb;
        const float* xp = xs + p * 8;
        #pragma unroll
        for (int s = 0; s < 16; s++) acc = fmaf(xp[s], wr[s], acc);
        hp[p * DM + d] = acc;
    }
}

// ---------------- K3a: scores (21504x512x128), bf16x2 output ----------------
__global__ void __launch_bounds__(128) k_scores(const float* __restrict__ mk) {
    __shared__ uint32_t As[64][WP], Bs[64][WP];
    float acc[2][4][4];
    #pragma unroll
    for (int i = 0; i < 2; i++)
        #pragma unroll
        for (int j = 0; j < 4; j++)
            #pragma unroll
            for (int c = 0; c < 4; c++) acc[i][j][c] = 0.f;
    int m0 = blockIdx.x * 64, n0 = blockIdx.y * 64;
    gemm_bf16_64(g_h, DM, mk + (size_t)n0 * DM, DM, 64, m0, DM, 1 << 30, As, Bs, acc);
    int lane = threadIdx.x & 31, wid = threadIdx.x >> 5;
    int warpM = wid & 1, warpN = wid >> 1;
    int g = lane >> 2, tg = lane & 3;
    #pragma unroll
    for (int mi = 0; mi < 2; mi++)
        #pragma unroll
        for (int ni = 0; ni < 4; ni++) {
            int row = m0 + warpM * 32 + mi * 16 + g;
            int col = n0 + warpN * 32 + ni * 8 + tg * 2;
            g_psb[(size_t)row * 256 + (col >> 1)] = pack_bf(acc[mi][ni][0], acc[mi][ni][1]);
            g_psb[(size_t)(row + 8) * 256 + (col >> 1)] = pack_bf(acc[mi][ni][2], acc[mi][ni][3]);
        }
}

// ---------------- K3b: row softmax (bf16 in place) ----------------
__global__ void k_softmax() {
    int tid = threadIdx.x, lane = tid & 31, w = tid >> 5;
    int row = blockIdx.x * 4 + w;
    uint4* base4 = (uint4*)(g_psb + (size_t)row * 256);
    uint4 raw[2];
    raw[0] = base4[lane * 2]; raw[1] = base4[lane * 2 + 1];
    float vals[16];
    #pragma unroll
    for (int j = 0; j < 2; j++) {
        uint32_t* wp = (uint32_t*)&raw[j];
        #pragma unroll
        for (int k = 0; k < 4; k++) {
            float2 f = __bfloat1622float2(*(__nv_bfloat162*)&wp[k]);
            vals[j * 8 + k * 2] = f.x; vals[j * 8 + k * 2 + 1] = f.y;
        }
    }
    float mx = -1e30f;
    #pragma unroll
    for (int i = 0; i < 16; i++) mx = fmaxf(mx, vals[i]);
    #pragma unroll
    for (int o = 16; o; o >>= 1) mx = fmaxf(mx, __shfl_xor_sync(0xffffffffu, mx, o));
    float sum = 0.f;
    #pragma unroll
    for (int i = 0; i < 16; i++) { vals[i] = __expf(vals[i] - mx); sum += vals[i]; }
    #pragma unroll
    for (int o = 16; o; o >>= 1) sum += __shfl_xor_sync(0xffffffffu, sum, o);
    float inv = 1.0f / sum;
    #pragma unroll
    for (int j = 0; j < 2; j++) {
        uint32_t* wp = (uint32_t*)&raw[j];
        #pragma unroll
        for (int k = 0; k < 4; k++)
            wp[k] = pack_bf(vals[j * 8 + k * 2] * inv, vals[j * 8 + k * 2 + 1] * inv);
    }
    base4[lane * 2] = raw[0]; base4[lane * 2 + 1] = raw[1];
}

// ---------------- K3c: AV (21504x128x512) + LN + GELU + residual ----------------
// 256 threads, tile 64x128, A read directly as bf16 words.
__global__ void __launch_bounds__(256) k_av(const float* __restrict__ mv,
                     const float* __restrict__ lnw, const float* __restrict__ lnb) {
    __shared__ uint32_t As[64][WP];
    __shared__ uint32_t Bs[128][WP];
    __shared__ float Cs[64][130];
    int tid = threadIdx.x;
    int lane = tid & 31, wid = tid >> 5;
    int warpM = wid & 1, warpN = wid >> 1;
    int g = lane >> 2, tg = lane & 3;
    int m0 = blockIdx.x * 64;
    float acc[2][4][4];
    #pragma unroll
    for (int i = 0; i < 2; i++)
        #pragma unroll
        for (int j = 0; j < 4; j++)
            #pragma unroll
            for (int c = 0; c < 4; c++) acc[i][j][c] = 0.f;
    for (int k0 = 0; k0 < SEA; k0 += 32) {
        {
            int row = tid >> 2, q = tid & 3;
            uint4 v = *(const uint4*)&g_psb[(size_t)(m0 + row) * 256 + (k0 >> 1) + q * 4];
            *(uint4*)&As[row][q * 4] = v;
        }
        #pragma unroll
        for (int u = 0; u < 4; u++) {
            int f = tid * 4 + u, row = f >> 3, q = f & 7;
            float4 v = *(const float4*)(mv + (size_t)row * SEA + k0 + q * 4);
            *(uint2*)&Bs[row][q * 2] = make_uint2(pack_bf(v.x, v.y), pack_bf(v.z, v.w));
        }
        __syncthreads();
        #pragma unroll
        for (int ks = 0; ks < 2; ks++) {
            int kk = ks * 8;
            uint32_t a[2][4], b[4][2];
            #pragma unroll
            for (int mi = 0; mi < 2; mi++) {
                int mr = warpM * 32 + mi * 16;
                a[mi][0] = As[mr + g][kk + tg];
                a[mi][1] = As[mr + g + 8][kk + tg];
                a[mi][2] = As[mr + g][kk + tg + 4];
                a[mi][3] = As[mr + g + 8][kk + tg + 4];
            }
            #pragma unroll
            for (int ni = 0; ni < 4; ni++) {
                int nr = warpN * 32 + ni * 8 + g;
                b[ni][0] = Bs[nr][kk + tg];
                b[ni][1] = Bs[nr][kk + tg + 4];
            }
            #pragma unroll
            for (int mi = 0; mi < 2; mi++)
                #pragma unroll
                for (int ni = 0; ni < 4; ni++)
                    mma_bf16(acc[mi][ni], a[mi], b[ni]);
        }
        __syncthreads();
    }
    #pragma unroll
    for (int mi = 0; mi < 2; mi++)
        #pragma unroll
        for (int ni = 0; ni < 4; ni++) {
            int row = warpM * 32 + mi * 16 + g;
            int col = warpN * 32 + ni * 8 + tg * 2;
            *(float2*)&Cs[row][col] = make_float2(acc[mi][ni][0], acc[mi][ni][1]);
            *(float2*)&Cs[row + 8][col] = make_float2(acc[mi][ni][2], acc[mi][ni][3]);
        }
    __syncthreads();
    int w = tid >> 5;
    for (int it = 0; it < 8; it++) {
        int r = w * 8 + it;
        int gr = m0 + r;
        float vv[4], s = 0.f, q = 0.f;
        #pragma unroll
        for (int qq = 0; qq < 4; qq++) {
            vv[qq] = Cs[r][lane + qq * 32];
            s += vv[qq]; q += vv[qq] * vv[qq];
        }
        #pragma unroll
        for (int o = 16; o; o >>= 1) {
            s += __shfl_xor_sync(0xffffffffu, s, o);
            q += __shfl_xor_sync(0xffffffffu, q, o);
        }
        float mu = s * (1.0f / DM);
        float var = q * (1.0f / DM) - mu * mu;
        float istd = rsqrtf(var + EPS_F);
        #pragma unroll
        for (int qq = 0; qq < 4; qq++) {
            int d = lane + qq * 32;
            float ln = (vv[qq] - mu) * istd * lnw[d] + lnb[d];
            g_hb[(size_t)gr * DM + d] = gelu_exact(ln) + g_h[(size_t)gr * DM + d];
        }
    }
}

// ---------------- K4: in_proj + fused depthwise conv + SiLU ----------------
// grid (336, 8). n0<256 -> xc channels with conv; n0>=256 -> z raw.
__global__ void __launch_bounds__(128) k_inproj(const float* __restrict__ W,
                        const float* __restrict__ cw, const float* __restrict__ cbv) {
    __shared__ uint32_t As[64][WP], Bs[64][WP];
    __shared__ float Cs[64][68];
    float acc[2][4][4];
    #pragma unroll
    for (int i = 0; i < 2; i++)
        #pragma unroll
        for (int j = 0; j < 4; j++)
            #pragma unroll
            for (int c = 0; c < 4; c++) acc[i][j][c] = 0.f;
    int m0 = blockIdx.x * 64, n0 = blockIdx.y * 64;
    gemm_bf16_64(g_hb, DM, W + (size_t)n0 * DM, DM, 64, m0, DM, 1 << 30, As, Bs, acc);
    int tid = threadIdx.x;
    int lane = tid & 31, wid = tid >> 5;
    int warpM = wid & 1, warpN = wid >> 1;
    int g = lane >> 2, tg = lane & 3;
    if (n0 >= 256) {
        int cb = n0 - 256;
        #pragma unroll
        for (int mi = 0; mi < 2; mi++)
            #pragma unroll
            for (int ni = 0; ni < 4; ni++) {
                int row = m0 + warpM * 32 + mi * 16 + g;
                int col = cb + warpN * 32 + ni * 8 + tg * 2;
                *(float2*)&g_z[(size_t)row * DIN + col] = make_float2(acc[mi][ni][0], acc[mi][ni][1]);
                *(float2*)&g_z[(size_t)(row + 8) * DIN + col] = make_float2(acc[mi][ni][2], acc[mi][ni][3]);
            }
        return;
    }
    // xc tile: stage into Cs (rows = 64 tokens of sequence bv = m0/64)
    #pragma unroll
    for (int mi = 0; mi < 2; mi++)
        #pragma unroll
        for (int ni = 0; ni < 4; ni++) {
            int row = warpM * 32 + mi * 16 + g;
            int col = warpN * 32 + ni * 8 + tg * 2;
            *(float2*)&Cs[row][col] = make_float2(acc[mi][ni][0], acc[mi][ni][1]);
            *(float2*)&Cs[row + 8][col] = make_float2(acc[mi][ni][2], acc[mi][ni][3]);
        }
    __syncthreads();
    int cb = n0;
    for (int idx = tid; idx < 64 * 64; idx += 128) {
        int l = idx >> 6, c = idx & 63;
        int gc = cb + c;
        float x0 = (l >= 3) ? Cs[l - 3][c] : 0.f;
        float x1 = (l >= 2) ? Cs[l - 2][c] : 0.f;
        float x2 = (l >= 1) ? Cs[l - 1][c] : 0.f;
        float x3 = Cs[l][c];
        const float4 wv = *(const float4*)(cw + gc * 4);
        float t = fmaf(x0, wv.x, fmaf(x1, wv.y, fmaf(x2, wv.z, fmaf(x3, wv.w, cbv[gc]))));
        g_xcc[(size_t)(m0 + l) * DIN + gc] = silu_f(t);
    }
}

// ---------------- K5: x_proj GEMM (21504 x 40 x 256) ----------------
__global__ void __launch_bounds__(128) k_xprojg(const float* __restrict__ xpw) {
    __shared__ uint32_t As[64][WP], Bs[64][WP];
    float acc[2][4][4];
    #pragma unroll
    for (int i = 0; i < 2; i++)
        #pragma unroll
        for (int j = 0; j < 4; j++)
            #pragma unroll
            for (int c = 0; c < 4; c++) acc[i][j][c] = 0.f;
    int m0 = blockIdx.x * 64;
    gemm_bf16_64(g_xcc, DIN, xpw, DIN, 40, m0, DIN, 1 << 30, As, Bs, acc);
    int lane = threadIdx.x & 31, wid = threadIdx.x >> 5;
    int warpM = wid & 1, warpN = wid >> 1;
    int g = lane >> 2, tg = lane & 3;
    #pragma unroll
    for (int mi = 0; mi < 2; mi++)
        #pragma unroll
        for (int ni = 0; ni < 4; ni++) {
            int row = m0 + warpM * 32 + mi * 16 + g;
            int col = warpN * 32 + ni * 8 + tg * 2;
            if (col < 40) {
                *(float2*)&g_dbl[(size_t)row * 40 + col] = make_float2(acc[mi][ni][0], acc[mi][ni][1]);
                *(float2*)&g_dbl[(size_t)(row + 8) * 40 + col] = make_float2(acc[mi][ni][2], acc[mi][ni][3]);
            }
        }
}

// ---------------- K6: scan (+ fused dt_proj + softplus) ----------------
__global__ void k_scan(const float* __restrict__ A_log, const float* __restrict__ D_ssm,
                       const float* __restrict__ dtw, const float* __restrict__ dtb) {
    int bv = blockIdx.x, c = threadIdx.x;   // 256
    __shared__ float dbl[LSEQ][40];
    for (int i = c; i < LSEQ * 40; i += 256)
        dbl[i / 40][i % 40] = g_dbl[(size_t)bv * LSEQ * 40 + i];
    float dw[8];
    #pragma unroll
    for (int r = 0; r < 8; r++) dw[r] = dtw[c * 8 + r];
    float db = dtb[c];
    float As[DSS];
    #pragma unroll
    for (int s = 0; s < DSS; s++) As[s] = -expf(A_log[c * DSS + s]);
    float Dv = D_ssm[c];
    float st[DSS];
    #pragma unroll
    for (int s = 0; s < DSS; s++) st[s] = 0.f;
    __syncthreads();
    size_t base = (size_t)bv * LSEQ * DIN;
    for (int l = 0; l < LSEQ; l++) {
        float dt = db;
        #pragma unroll
        for (int r = 0; r < 8; r++) dt = fmaf(dbl[l][r], dw[r], dt);
        float d = (dt > 20.f) ? dt : log1pf(expf(dt));
        float u  = g_xcc[base + l * DIN + c];
        float zv = g_z  [base + l * DIN + c];
        float du = d * u;
        float y = 0.f;
        #pragma unroll
        for (int s = 0; s < DSS; s++) {
            float dA = __expf(d * As[s]);
            st[s] = fmaf(st[s], dA, du * dbl[l][8 + s]);
            y = fmaf(st[s], dbl[l][24 + s], y);
        }
        y = fmaf(Dv, u, y);
        y *= silu_f(zv);
        g_y[base + l * DIN + c] = y;
    }
}

// ---------------- K7: out_proj (21504x128x256) ----------------
__global__ void __launch_bounds__(128) k_outproj(const float* __restrict__ W) {
    __shared__ uint32_t As[64][WP], Bs[64][WP];
    float acc[2][4][4];
    #pragma unroll
    for (int i = 0; i < 2; i++)
        #pragma unroll
        for (int j = 0; j < 4; j++)
            #pragma unroll
            for (int c = 0; c < 4; c++) acc[i][j][c] = 0.f;
    int m0 = blockIdx.x * 64, n0 = blockIdx.y * 64;
    gemm_bf16_64(g_y, DIN, W + (size_t)n0 * DIN, DIN, 64, m0, DIN, 1 << 30, As, Bs, acc);
    int lane = threadIdx.x & 31, wid = threadIdx.x >> 5;
    int warpM = wid & 1, warpN = wid >> 1;
    int g = lane >> 2, tg = lane & 3;
    #pragma unroll
    for (int mi = 0; mi < 2; mi++)
        #pragma unroll
        for (int ni = 0; ni < 4; ni++) {
            int row = m0 + warpM * 32 + mi * 16 + g;
            int col = n0 + warpN * 32 + ni * 8 + tg * 2;
            *(float2*)&g_mo[(size_t)row * DM + col] = make_float2(acc[mi][ni][0], acc[mi][ni][1]);
            *(float2*)&g_mo[(size_t)(row + 8) * DM + col] = make_float2(acc[mi][ni][2], acc[mi][ni][3]);
        }
}

// ---------------- K8a: mlp2 split-K partials ----------------
__global__ void __launch_bounds__(128) k_mlp2p(const float* __restrict__ W) {
    __shared__ uint32_t As[64][WP], Bs[64][WP];
    float acc[2][4][4];
    #pragma unroll
    for (int i = 0; i < 2; i++)
        #pragma unroll
        for (int j = 0; j < 4; j++)
            #pragma unroll
            for (int c = 0; c < 4; c++) acc[i][j][c] = 0.f;
    int m0 = blockIdx.x * 64, n0 = blockIdx.y * 64, s = blockIdx.z;
    const float* A = g_mo + (size_t)s * 512;
    const float* B = W + (size_t)n0 * 8192 + (size_t)s * 512;
    gemm_bf16_64(A, 8192, B, 8192, 64, m0, 512, NBV, As, Bs, acc);
    int lane = threadIdx.x & 31, wid = threadIdx.x >> 5;
    int warpM = wid & 1, warpN = wid >> 1;
    int g = lane >> 2, tg = lane & 3;
    #pragma unroll
    for (int mi = 0; mi < 2; mi++)
        #pragma unroll
        for (int ni = 0; ni < 4; ni++) {
            int row = m0 + warpM * 32 + mi * 16 + g;
            int col = n0 + warpN * 32 + ni * 8 + tg * 2;
            if (row < NBV)
                *(float2*)&g_t2p[((size_t)s * NBV + row) * 192 + col] =
                    make_float2(acc[mi][ni][0], acc[mi][ni][1]);
            if (row + 8 < NBV)
                *(float2*)&g_t2p[((size_t)s * NBV + row + 8) * 192 + col] =
                    make_float2(acc[mi][ni][2], acc[mi][ni][3]);
        }
}

// ---------------- K8b: reduce + GELU + mlp3 + denorm ----------------
__global__ void k_mlp2fin3(const float* __restrict__ bias2,
                           const float* __restrict__ W3, const float* __restrict__ b3,
                           const float* __restrict__ rw, const float* __restrict__ rb,
                           float* __restrict__ out) {
    int bv = blockIdx.x;
    int b = bv / NVAR, v = bv % NVAR;
    int tid = threadIdx.x;   // 192
    __shared__ float ts[192];
    float sum = 0.f;
    #pragma unroll
    for (int s = 0; s < 16; s++) sum += g_t2p[((size_t)s * NBV + bv) * 192 + tid];
    ts[tid] = gelu_exact(sum + bias2[tid]);
    __syncthreads();
    if (tid < PRED) {
        float acc = b3[tid];
        const float* w = W3 + tid * 192;
        #pragma unroll 4
        for (int j = 0; j < 192; j++) acc = fmaf(ts[j], w[j], acc);
        float val = (acc - rb[v]) / (rw[v] + 1e-10f) * g_std[bv] + g_mean[bv];
        out[((size_t)b * PRED + tid) * NVAR + v] = val;
    }
}

// ---------------- launch ----------------
extern "C" void kernel_launch(void* const* d_in, const int* in_sizes, int n_in,
                              void* d_out, int out_size) {
    const float* x         = (const float*)d_in[0];
    const float* revin_w   = (const float*)d_in[1];
    const float* revin_b   = (const float*)d_in[2];
    const float* mlp1_w    = (const float*)d_in[3];
    const float* mlp1_b    = (const float*)d_in[4];
    const float* mk_w      = (const float*)d_in[5];
    const float* mv_w      = (const float*)d_in[6];
    const float* ln_w      = (const float*)d_in[7];
    const float* ln_b      = (const float*)d_in[8];
    const float* in_proj_w = (const float*)d_in[9];
    const float* conv_w    = (const float*)d_in[10];
    const float* conv_b    = (const float*)d_in[11];
    const float* x_proj_w  = (const float*)d_in[12];
    const float* dt_proj_w = (const float*)d_in[13];
    const float* dt_proj_b = (const float*)d_in[14];
    const float* A_log     = (const float*)d_in[15];
    const float* D_ssm     = (const float*)d_in[16];
    const float* out_proj_w= (const float*)d_in[17];
    const float* mlp2_w    = (const float*)d_in[18];
    const float* mlp2_b    = (const float*)d_in[19];
    const float* mlp3_w    = (const float*)d_in[20];
    const float* mlp3_b    = (const float*)d_in[21];
    float* out = (float*)d_out;

    k_revin   <<<NBV, 512>>>(x, revin_w, revin_b);
    k_mlp1    <<<NBV, 128>>>(mlp1_w, mlp1_b);
    k_scores  <<<dim3(MROWS / 64, SEA / 64), 128>>>(mk_w);
    k_softmax <<<MROWS / 4, 128>>>();
    k_av      <<<MROWS / 64, 256>>>(mv_w, ln_w, ln_b);
    k_inproj  <<<dim3(MROWS / 64, 8), 128>>>(in_proj_w, conv_w, conv_b);
    k_xprojg  <<<MROWS / 64, 128>>>(x_proj_w);
    k_scan    <<<NBV, 256>>>(A_log, D_ssm, dt_proj_w, dt_proj_b);
    k_outproj <<<dim3(MROWS / 64, 2), 128>>>(out_proj_w);
    k_mlp2p   <<<dim3(6, 3, 16), 128>>>(mlp2_w);
    k_mlp2fin3<<<NBV, 192>>>(mlp2_b, mlp3_w, mlp3_b, revin_w, revin_b, out);
}